// round 11
// baseline (speedup 1.0000x reference)
#include <cuda_runtime.h>
#include <cuda_bf16.h>

#define NNODES 50000
#define NROWSP 50048            // 391 * 128, padded row count for GEMM operands
#define FIN    128
#define DDIM   64
#define HDIM   128
#define BGRAPH 16
#define E1N    800000
#define E2N    200000
#define AREG   2000
#define SLOTS  2048
#define BMWORDS 1568

typedef unsigned long long ull;
typedef unsigned int u32;

// ---------------- helpers -------------------------------------------------------
__device__ __forceinline__ ull ffma2(ull a, ull b, ull c) {
    ull d;
    asm("fma.rn.f32x2 %0, %1, %2, %3;" : "=l"(d) : "l"(a), "l"(b), "l"(c));
    return d;
}
__device__ __forceinline__ ull pack2(float lo, float hi) {
    ull r;
    asm("mov.b64 %0, {%1, %2};" : "=l"(r) : "f"(lo), "f"(hi));
    return r;
}
__device__ __forceinline__ void unpack2(ull v, float& lo, float& hi) {
    asm("mov.b64 {%0, %1}, %2;" : "=f"(lo), "=f"(hi) : "l"(v));
}
__device__ __forceinline__ u32 bf2_hi(float a, float b) {
    __nv_bfloat162 h = __floats2bfloat162_rn(a, b);
    return *reinterpret_cast<u32*>(&h);
}
__device__ __forceinline__ u32 bf2_lo(float a, float b) {
    float ra = a - __bfloat162float(__float2bfloat16(a));
    float rb = b - __bfloat162float(__float2bfloat16(b));
    __nv_bfloat162 l = __floats2bfloat162_rn(ra, rb);
    return *reinterpret_cast<u32*>(&l);
}
__device__ __forceinline__ void mma16816(float* c, u32 a0, u32 a1, u32 a2, u32 a3,
                                         u32 b0, u32 b1) {
    asm("mma.sync.aligned.m16n8k16.row.col.f32.bf16.bf16.f32 "
        "{%0,%1,%2,%3}, {%4,%5,%6,%7}, {%8,%9}, {%0,%1,%2,%3};"
        : "+f"(c[0]), "+f"(c[1]), "+f"(c[2]), "+f"(c[3])
        : "r"(a0), "r"(a1), "r"(a2), "r"(a3), "r"(b0), "r"(b1));
}
__device__ __forceinline__ u32 smem_u32(const void* p) {
    u32 a;
    asm("{ .reg .u64 t; cvta.to.shared.u64 t, %1; cvt.u32.u64 %0, t; }"
        : "=r"(a) : "l"(p));
    return a;
}
__device__ __forceinline__ void cpa16(u32 smem_addr, const void* gptr) {
    asm volatile("cp.async.cg.shared.global [%0], [%1], 16;"
                 :: "r"(smem_addr), "l"(gptr) : "memory");
}
#define CP_COMMIT() asm volatile("cp.async.commit_group;" ::: "memory")
#define CP_WAIT0()  asm volatile("cp.async.wait_group 0;" ::: "memory")

// pp permutation: pair jg (k = 2*jg within a 32-k chunk) -> u32 slot in 24-u32 row
__host__ __device__ __forceinline__ int pp_of(int jg) {
    return ((jg >> 2) & 1) + (jg & 3) * 2 + (jg >> 3) * 8;
}

// ---------------- scratch -------------------------------------------------------
__device__ __align__(16) float d_yl[NNODES * DDIM];
__device__ __align__(16) float d_yr[NNODES * DDIM];
__device__ __align__(16) float d_agg1[NNODES * DDIM];
__device__ __align__(16) float d_deg1[NNODES];
__device__ __align__(16) float d_gl[NNODES * DDIM];
__device__ __align__(16) float d_gr[NNODES * DDIM];
__device__ __align__(16) int   d_slotmap[BGRAPH * NNODES];
__device__ __align__(16) unsigned d_bitmap[BGRAPH * BMWORDS];
__device__ __align__(16) int   d_counter[BGRAPH];
__device__ __align__(16) float d_acc2[BGRAPH * SLOTS * DDIM];
__device__ __align__(16) float d_deg2[BGRAPH * SLOTS];
__device__ __align__(16) float d_u[BGRAPH * HDIM];
__device__ __align__(16) float d_c[BGRAPH];
// preconverted bf16-split operands, pair-permuted, 24 u32 per row (48-bf16 stride)
__device__ __align__(16) u32 d_xh[4 * NROWSP * 24];
__device__ __align__(16) u32 d_xl[4 * NROWSP * 24];
__device__ __align__(16) u32 d_h1h[2 * NROWSP * 24];
__device__ __align__(16) u32 d_h1l[2 * NROWSP * 24];
__device__ __align__(16) u32 d_B1h[4 * 128 * 24];
__device__ __align__(16) u32 d_B1l[4 * 128 * 24];
__device__ __align__(16) u32 d_B2h[2 * 128 * 24];
__device__ __align__(16) u32 d_B2l[2 * 128 * 24];

// ---------------- clear kernel --------------------------------------------------
static constexpr int CLR_AGG1 = NNODES * DDIM / 4;
static constexpr int CLR_ACC2 = BGRAPH * SLOTS * DDIM / 4;
static constexpr int CLR_SMAP = BGRAPH * NNODES / 4;
static constexpr int CLR_BMAP = BGRAPH * BMWORDS / 4;
static constexpr int CLR_DEG1 = NNODES / 4;
static constexpr int CLR_DEG2 = BGRAPH * SLOTS / 4;
static constexpr int CLR_CNT  = BGRAPH / 4;
static constexpr int CLR_TOTAL = CLR_AGG1 + CLR_ACC2 + CLR_SMAP + CLR_BMAP +
                                 CLR_DEG1 + CLR_DEG2 + CLR_CNT;

__global__ void clear_kernel() {
    int i = blockIdx.x * blockDim.x + threadIdx.x;
    float4 z = make_float4(0.f, 0.f, 0.f, 0.f);
    if (i < CLR_AGG1) { ((float4*)d_agg1)[i] = z; return; }
    i -= CLR_AGG1;
    if (i < CLR_ACC2) { ((float4*)d_acc2)[i] = z; return; }
    i -= CLR_ACC2;
    if (i < CLR_SMAP) { ((int4*)d_slotmap)[i] = make_int4(-1, -1, -1, -1); return; }
    i -= CLR_SMAP;
    if (i < CLR_BMAP) { ((uint4*)d_bitmap)[i] = make_uint4(0, 0, 0, 0); return; }
    i -= CLR_BMAP;
    if (i < CLR_DEG1) { ((float4*)d_deg1)[i] = z; return; }
    i -= CLR_DEG1;
    if (i < CLR_DEG2) { ((float4*)d_deg2)[i] = z; return; }
    i -= CLR_DEG2;
    if (i < CLR_CNT)  { ((int4*)d_counter)[i] = make_int4(0, 0, 0, 0); }
}

// ---------------- weight preconversion (B1: K=128, B2: K=64) --------------------
__global__ void prep_w_kernel(const float* __restrict__ W1l,
                              const float* __restrict__ W1r,
                              const float* __restrict__ W2l,
                              const float* __restrict__ W2r) {
    int tid = blockIdx.x * blockDim.x + threadIdx.x;
    if (tid >= 768) return;
    if (tid < 512) {               // B1: 4 chunks x 128 n
        int c = tid >> 7, n = tid & 127;
        const float* W = (n < 64) ? W1l : W1r;
        int nc = n & 63;
        u32* oh = d_B1h + (c * 128 + n) * 24;
        u32* ol = d_B1l + (c * 128 + n) * 24;
#pragma unroll
        for (int jg = 0; jg < 16; jg++) {
            int k = c * 32 + 2 * jg;
            float wx = W[k * 64 + nc];
            float wy = W[(k + 1) * 64 + nc];
            int pp = pp_of(jg);
            oh[pp] = bf2_hi(wx, wy);
            ol[pp] = bf2_lo(wx, wy);
        }
    } else {                       // B2: 2 chunks x 128 n
        int id = tid - 512;
        int c = id >> 7, n = id & 127;
        const float* W = (n < 64) ? W2l : W2r;
        int nc = n & 63;
        u32* oh = d_B2h + (c * 128 + n) * 24;
        u32* ol = d_B2l + (c * 128 + n) * 24;
#pragma unroll
        for (int jg = 0; jg < 16; jg++) {
            int k = c * 32 + 2 * jg;
            float wx = W[k * 64 + nc];
            float wy = W[(k + 1) * 64 + nc];
            int pp = pp_of(jg);
            oh[pp] = bf2_hi(wx, wy);
            ol[pp] = bf2_lo(wx, wy);
        }
    }
}

// ---------------- x preconversion: x[N,128] -> xh/xl [4][NROWSP][24] ------------
__global__ void prep_x_kernel(const float* __restrict__ x) {
    int row = blockIdx.x * blockDim.x + threadIdx.x;
    int c = blockIdx.y;
    if (row >= NROWSP) return;
    u32* oh = d_xh + (c * NROWSP + row) * 24;
    u32* ol = d_xl + (c * NROWSP + row) * 24;
    if (row >= NNODES) {
#pragma unroll
        for (int i = 0; i < 16; i++) { oh[i] = 0; ol[i] = 0; }
        return;
    }
    const float2* src = (const float2*)(x + (long)row * 128 + c * 32);
#pragma unroll
    for (int jg = 0; jg < 16; jg++) {
        float2 v = src[jg];
        int pp = pp_of(jg);
        oh[pp] = bf2_hi(v.x, v.y);
        ol[pp] = bf2_lo(v.x, v.y);
    }
}

// ---------------- h1 compute + preconversion ------------------------------------
__global__ void prep_h1_kernel() {
    int row = blockIdx.x * blockDim.x + threadIdx.x;
    int c = blockIdx.y;
    if (row >= NROWSP) return;
    u32* oh = d_h1h + (c * NROWSP + row) * 24;
    u32* ol = d_h1l + (c * NROWSP + row) * 24;
    if (row >= NNODES) {
#pragma unroll
        for (int i = 0; i < 16; i++) { oh[i] = 0; ol[i] = 0; }
        return;
    }
    float inv = 1.f / fmaxf(d_deg1[row], 1.f);
    const float2* ag = (const float2*)(d_agg1 + row * 64 + c * 32);
    const float2* yv = (const float2*)(d_yr + row * 64 + c * 32);
#pragma unroll
    for (int jg = 0; jg < 16; jg++) {
        float2 a = ag[jg];
        float2 y = yv[jg];
        float vx = fmaxf(a.x * inv + y.x, 0.f);
        float vy = fmaxf(a.y * inv + y.y, 0.f);
        int pp = pp_of(jg);
        oh[pp] = bf2_hi(vx, vy);
        ol[pp] = bf2_lo(vx, vy);
    }
}

// ================= HMMA dual GEMM, cp.async double-buffered =====================
// D[128,128] = A[128,K] @ [W1|W2]; operands pre-split/pre-permuted in global.
// smem: 2 buffers x 4 slabs (Ah, Al, Bh, Bl) x 12KB = 96KB dynamic.
template <int NC>
__global__ __launch_bounds__(256) void mma_gemm_cp(const u32* __restrict__ Agh,
                                                   const u32* __restrict__ Agl,
                                                   const u32* __restrict__ Bgh,
                                                   const u32* __restrict__ Bgl,
                                                   const float* __restrict__ bias,
                                                   float* __restrict__ C1,
                                                   float* __restrict__ C2,
                                                   int nrows) {
    extern __shared__ u32 sm[];
    const int t = threadIdx.x;
    const int w = t >> 5, lane = t & 31;
    const int g = lane >> 2, tg = lane & 3;
    const int row0 = blockIdx.x * 128;

    float acc[16][4];
#pragma unroll
    for (int nt = 0; nt < 16; nt++)
#pragma unroll
        for (int i = 0; i < 4; i++) acc[nt][i] = 0.f;

    auto copy_chunk = [&](int c, int buf) {
        u32 sbase = smem_u32(sm + buf * 12288);
        const u32* sA_h = Agh + (c * NROWSP + row0) * 24;
        const u32* sA_l = Agl + (c * NROWSP + row0) * 24;
        const u32* sB_h = Bgh + c * 3072;
        const u32* sB_l = Bgl + c * 3072;
#pragma unroll
        for (int i = 0; i < 3; i++) {
            int idx = t + i * 256;            // 0..767 granules per slab
            cpa16(sbase + 0 * 12288 + idx * 16, sA_h + idx * 4);
            cpa16(sbase + 1 * 12288 + idx * 16, sA_l + idx * 4);
            cpa16(sbase + 2 * 12288 + idx * 16, sB_h + idx * 4);
            cpa16(sbase + 3 * 12288 + idx * 16, sB_l + idx * 4);
        }
        CP_COMMIT();
    };

    copy_chunk(0, 0);

    for (int c = 0; c < NC; c++) {
        CP_WAIT0();
        __syncthreads();
        if (c + 1 < NC) copy_chunk(c + 1, (c + 1) & 1);

        const __nv_bfloat16* base = (const __nv_bfloat16*)(sm + (c & 1) * 12288);
        const __nv_bfloat16* sAh = base;
        const __nv_bfloat16* sAl = base + 6144;
        const __nv_bfloat16* sBh = base + 12288;
        const __nv_bfloat16* sBl = base + 18432;

#pragma unroll
        for (int ks = 0; ks < 2; ks++) {
            ull ah0 = *(const ull*)(sAh + (w * 16 + g) * 48 + ks * 16 + tg * 4);
            ull ah1 = *(const ull*)(sAh + (w * 16 + g + 8) * 48 + ks * 16 + tg * 4);
            ull al0 = *(const ull*)(sAl + (w * 16 + g) * 48 + ks * 16 + tg * 4);
            ull al1 = *(const ull*)(sAl + (w * 16 + g + 8) * 48 + ks * 16 + tg * 4);
            u32 h0 = (u32)ah0, h2 = (u32)(ah0 >> 32);
            u32 h1 = (u32)ah1, h3 = (u32)(ah1 >> 32);
            u32 l0 = (u32)al0, l2 = (u32)(al0 >> 32);
            u32 l1 = (u32)al1, l3 = (u32)(al1 >> 32);
#pragma unroll
            for (int nt = 0; nt < 16; nt++) {
                ull bh = *(const ull*)(sBh + (nt * 8 + g) * 48 + ks * 16 + tg * 4);
                u32 bh0 = (u32)bh, bh1 = (u32)(bh >> 32);
                mma16816(acc[nt], h0, h1, h2, h3, bh0, bh1);
                mma16816(acc[nt], l0, l1, l2, l3, bh0, bh1);
                ull bl = *(const ull*)(sBl + (nt * 8 + g) * 48 + ks * 16 + tg * 4);
                mma16816(acc[nt], h0, h1, h2, h3, (u32)bl, (u32)(bl >> 32));
            }
        }
        __syncthreads();
    }

    // ---- store ----
    int r0 = row0 + w * 16 + g;
#pragma unroll
    for (int nt = 0; nt < 16; nt++) {
        int col = nt * 8 + tg * 2;
        if (col < 64) {
            if (r0 < nrows)
                *(float2*)(C1 + (long)r0 * 64 + col) = make_float2(acc[nt][0], acc[nt][1]);
            if (r0 + 8 < nrows)
                *(float2*)(C1 + (long)(r0 + 8) * 64 + col) = make_float2(acc[nt][2], acc[nt][3]);
        } else {
            int c2 = col - 64;
            float2 bb = *(const float2*)(bias + c2);
            if (r0 < nrows)
                *(float2*)(C2 + (long)r0 * 64 + c2) =
                    make_float2(acc[nt][0] + bb.x, acc[nt][1] + bb.y);
            if (r0 + 8 < nrows)
                *(float2*)(C2 + (long)(r0 + 8) * 64 + c2) =
                    make_float2(acc[nt][2] + bb.x, acc[nt][3] + bb.y);
        }
    }
}

// ---------------- conv1 edge scatter (8 edges/warp) -----------------------------
__global__ void scatter1_kernel(const int* __restrict__ ei) {
    int tid = blockIdx.x * blockDim.x + threadIdx.x;
    int w = tid >> 5, lane = tid & 31;
    int e0 = 8 * w + (lane >> 4);
    int j = lane & 15;

    int s0 = ei[e0];
    int s1 = ei[e0 + 2];
    int s2 = ei[e0 + 4];
    int s3 = ei[e0 + 6];
    int dd0 = ei[E1N + e0];
    int dd1 = ei[E1N + e0 + 2];
    int dd2 = ei[E1N + e0 + 4];
    int dd3 = ei[E1N + e0 + 6];

    float4 v0 = ((const float4*)(d_yl + s0 * 64))[j];
    float4 v1 = ((const float4*)(d_yl + s1 * 64))[j];
    float4 v2 = ((const float4*)(d_yl + s2 * 64))[j];
    float4 v3 = ((const float4*)(d_yl + s3 * 64))[j];

    float* p0 = d_agg1 + dd0 * 64 + 4 * j;
    float* p1 = d_agg1 + dd1 * 64 + 4 * j;
    float* p2 = d_agg1 + dd2 * 64 + 4 * j;
    float* p3 = d_agg1 + dd3 * 64 + 4 * j;
    asm volatile("red.global.add.v4.f32 [%0], {%1,%2,%3,%4};"
                 :: "l"(p0), "f"(v0.x), "f"(v0.y), "f"(v0.z), "f"(v0.w) : "memory");
    asm volatile("red.global.add.v4.f32 [%0], {%1,%2,%3,%4};"
                 :: "l"(p1), "f"(v1.x), "f"(v1.y), "f"(v1.z), "f"(v1.w) : "memory");
    asm volatile("red.global.add.v4.f32 [%0], {%1,%2,%3,%4};"
                 :: "l"(p2), "f"(v2.x), "f"(v2.y), "f"(v2.z), "f"(v2.w) : "memory");
    asm volatile("red.global.add.v4.f32 [%0], {%1,%2,%3,%4};"
                 :: "l"(p3), "f"(v3.x), "f"(v3.y), "f"(v3.z), "f"(v3.w) : "memory");
    if (j == 0) {
        atomicAdd(&d_deg1[dd0], 1.0f);
        atomicAdd(&d_deg1[dd1], 1.0f);
        atomicAdd(&d_deg1[dd2], 1.0f);
        atomicAdd(&d_deg1[dd3], 1.0f);
    }
}

// ---------------- slot assignment + bitmap --------------------------------------
__global__ void slot_kernel(const int* __restrict__ targets,
                            const int* __restrict__ regions) {
    int idx = blockIdx.x * blockDim.x + threadIdx.x;
    if (idx >= BGRAPH * (AREG + 1)) return;
    int b = idx / (AREG + 1);
    int j = idx % (AREG + 1);
    int node = (j == AREG) ? targets[b] : regions[b * AREG + j];
    atomicOr(&d_bitmap[b * BMWORDS + (node >> 5)], 1u << (node & 31));
    int* p = &d_slotmap[b * NNODES + node];
    if (atomicCAS(p, -1, -2) == -1) {
        int s = atomicAdd(&d_counter[b], 1);
        atomicExch(p, s);
    }
}

// ---------------- conv2 scatter with smem bitmap filter -------------------------
__global__ void scatter2_kernel(const int* __restrict__ ne) {
    __shared__ unsigned sbm[BMWORDS];
    const int b = blockIdx.y;
    for (int i = threadIdx.x; i < BMWORDS; i += 320)
        sbm[i] = d_bitmap[b * BMWORDS + i];
    __syncthreads();

    const int lane = threadIdx.x & 31;
    const long base = (long)b * 2 * E2N;
    int e0 = blockIdx.x * 1600 + threadIdx.x;
#pragma unroll
    for (int it = 0; it < 5; it++) {
        int e = e0 + it * 320;
        int dst = ne[base + E2N + e];
        bool hit = (sbm[dst >> 5] >> (dst & 31)) & 1u;
        int slot = -1, src = 0;
        if (hit) {
            slot = d_slotmap[b * NNODES + dst];
            src = ne[base + e];
        }
        unsigned mask = __ballot_sync(0xffffffffu, hit);
        while (mask) {
            int bit = __ffs(mask) - 1;
            mask &= mask - 1;
            int es = __shfl_sync(0xffffffffu, src, bit);
            int sl = __shfl_sync(0xffffffffu, slot, bit);
            float2 v = ((const float2*)(d_gl + es * 64))[lane];
            float* p = d_acc2 + (b * SLOTS + sl) * 64 + 2 * lane;
            asm volatile("red.global.add.v2.f32 [%0], {%1,%2};"
                         :: "l"(p), "f"(v.x), "f"(v.y) : "memory");
            if (lane == 0) atomicAdd(&d_deg2[b * SLOTS + sl], 1.0f);
        }
    }
}

// ---------------- u_b = Wo @ t_b , c_b = bo . t_b -------------------------------
__global__ void u_kernel(const int* __restrict__ targets,
                         const float* __restrict__ Wo,
                         const float* __restrict__ bo) {
    int idx = blockIdx.x * blockDim.x + threadIdx.x;
    if (idx >= BGRAPH * HDIM) return;
    int b = idx >> 7;
    int h = idx & 127;
    int node = targets[b];
    int s = d_slotmap[b * NNODES + node];
    int base = (b * SLOTS + s) * 64;
    float inv = 1.f / fmaxf(d_deg2[b * SLOTS + s], 1.f);
    float acc = 0.f, c = 0.f;
#pragma unroll
    for (int d = 0; d < 64; d++) {
        float td = fmaxf(d_acc2[base + d] * inv + d_gr[node * 64 + d], 0.f);
        acc += Wo[h * 64 + d] * td;
        c += bo[d] * td;
    }
    d_u[idx] = acc;
    if (h == 0) d_c[b] = c;
}

// ---------------- final readout -------------------------------------------------
__global__ void final_kernel(const int* __restrict__ regions,
                             const float* __restrict__ Wm,
                             const float* __restrict__ bm,
                             float* __restrict__ q) {
    __shared__ float sWm[64 * 128];
    __shared__ float sreg[8][8][64];
    for (int i = threadIdx.x; i < 64 * 128; i += blockDim.x)
        sWm[i] = Wm[i];
    __syncthreads();

    const int lane = threadIdx.x & 31;
    const int wl = threadIdx.x >> 5;
    const float2 bmp0 = ((const float2*)bm)[lane];
    const float2 bmp1 = ((const float2*)bm)[lane + 32];

    for (int tile = blockIdx.x * 8 + wl; tile < 4000; tile += gridDim.x * 8) {
        int b = tile / 250;
#pragma unroll
        for (int r = 0; r < 8; r++) {
            int p = tile * 8 + r;
            int node = regions[p];
            int s = d_slotmap[b * NNODES + node];
            int base = (b * SLOTS + s) * 64;
            float inv = 1.f / fmaxf(d_deg2[b * SLOTS + s], 1.f);
            float2 a = ((const float2*)(d_acc2 + base))[lane];
            float2 g = ((const float2*)(d_gr + node * 64))[lane];
            sreg[wl][r][2 * lane]     = fmaxf(a.x * inv + g.x, 0.f);
            sreg[wl][r][2 * lane + 1] = fmaxf(a.y * inv + g.y, 0.f);
        }
        __syncwarp();

        ull acc0[8], acc1[8];
#pragma unroll
        for (int r = 0; r < 8; r++) { acc0[r] = 0ull; acc1[r] = 0ull; }

#pragma unroll 8
        for (int d = 0; d < 64; d++) {
            ull w0 = ((const ull*)(sWm + d * 128))[lane];
            ull w1 = ((const ull*)(sWm + d * 128 + 64))[lane];
#pragma unroll
            for (int r = 0; r < 8; r++) {
                float rd = sreg[wl][r][d];
                ull rdp = pack2(rd, rd);
                acc0[r] = ffma2(rdp, w0, acc0[r]);
                acc1[r] = ffma2(rdp, w1, acc1[r]);
            }
        }

        const float2* ubp = (const float2*)(d_u + b * HDIM);
        float2 u0 = ubp[lane];
        float2 u1 = ubp[lane + 32];
        float cb = d_c[b];
#pragma unroll
        for (int r = 0; r < 8; r++) {
            float m0, m1, m2, m3;
            unpack2(acc0[r], m0, m1);
            unpack2(acc1[r], m2, m3);
            float sum = fmaxf(m0 + bmp0.x, 0.f) * u0.x
                      + fmaxf(m1 + bmp0.y, 0.f) * u0.y
                      + fmaxf(m2 + bmp1.x, 0.f) * u1.x
                      + fmaxf(m3 + bmp1.y, 0.f) * u1.y;
#pragma unroll
            for (int o = 16; o > 0; o >>= 1)
                sum += __shfl_down_sync(0xffffffffu, sum, o);
            if (lane == 0) q[tile * 8 + r] = sum + cb;
        }
        __syncwarp();
    }
}

// ---------------- launch ---------------------------------------------------------
extern "C" void kernel_launch(void* const* d_in, const int* in_sizes, int n_in,
                              void* d_out, int out_size) {
    const float* x       = (const float*)d_in[0];
    const int*   ei      = (const int*)  d_in[1];
    const int*   ne      = (const int*)  d_in[2];
    const int*   targets = (const int*)  d_in[3];
    const int*   regions = (const int*)  d_in[4];
    const float* W1l     = (const float*)d_in[5];
    const float* W1r     = (const float*)d_in[6];
    const float* b1      = (const float*)d_in[7];
    const float* W2l     = (const float*)d_in[8];
    const float* W2r     = (const float*)d_in[9];
    const float* b2      = (const float*)d_in[10];
    const float* Wm      = (const float*)d_in[11];
    const float* bm      = (const float*)d_in[12];
    const float* Wo      = (const float*)d_in[13];
    const float* bo      = (const float*)d_in[14];
    float* q = (float*)d_out;

    float *p_yl, *p_yr, *p_gl, *p_gr;
    u32 *p_xh, *p_xl, *p_h1h, *p_h1l, *p_B1h, *p_B1l, *p_B2h, *p_B2l;
    cudaGetSymbolAddress((void**)&p_yl, d_yl);
    cudaGetSymbolAddress((void**)&p_yr, d_yr);
    cudaGetSymbolAddress((void**)&p_gl, d_gl);
    cudaGetSymbolAddress((void**)&p_gr, d_gr);
    cudaGetSymbolAddress((void**)&p_xh, d_xh);
    cudaGetSymbolAddress((void**)&p_xl, d_xl);
    cudaGetSymbolAddress((void**)&p_h1h, d_h1h);
    cudaGetSymbolAddress((void**)&p_h1l, d_h1l);
    cudaGetSymbolAddress((void**)&p_B1h, d_B1h);
    cudaGetSymbolAddress((void**)&p_B1l, d_B1l);
    cudaGetSymbolAddress((void**)&p_B2h, d_B2h);
    cudaGetSymbolAddress((void**)&p_B2l, d_B2l);

    cudaFuncSetAttribute(mma_gemm_cp<4>,
                         cudaFuncAttributeMaxDynamicSharedMemorySize, 98304);
    cudaFuncSetAttribute(mma_gemm_cp<2>,
                         cudaFuncAttributeMaxDynamicSharedMemorySize, 98304);

    const int ROWBLK = (NROWSP + 255) / 256;   // 196

    // 0. clear scratch
    clear_kernel<<<(CLR_TOTAL + 255) / 256, 256>>>();

    // 1. weight preconversion
    prep_w_kernel<<<3, 256>>>(W1l, W1r, W2l, W2r);

    // 2. x preconversion (bf16 split, pair-permuted)
    {
        dim3 g(ROWBLK, 4);
        prep_x_kernel<<<g, 256>>>(x);
    }

    // 3. GEMM1: yl = x@W1l ; yr = x@W1r + b1   <-- profiled slot
    mma_gemm_cp<4><<<391, 256, 98304>>>(p_xh, p_xl, p_B1h, p_B1l, b1,
                                        p_yl, p_yr, NNODES);

    // 4. conv1 scatter
    {
        int warps = E1N / 8;
        int blocks = (warps * 32 + 255) / 256;
        scatter1_kernel<<<blocks, 256>>>(ei);
    }

    // 5. h1 compute + preconversion
    {
        dim3 g(ROWBLK, 2);
        prep_h1_kernel<<<g, 256>>>();
    }

    // 6. GEMM2: gl = h1@W2l ; gr = h1@W2r + b2
    mma_gemm_cp<2><<<391, 256, 98304>>>(p_h1h, p_h1l, p_B2h, p_B2l, b2,
                                        p_gl, p_gr, NNODES);

    // 7. slot assignment + bitmap
    slot_kernel<<<(BGRAPH * (AREG + 1) + 255) / 256, 256>>>(targets, regions);

    // 8. conv2 scatter with smem bitmap filter
    {
        dim3 grid(125, BGRAPH);
        scatter2_kernel<<<grid, 320>>>(ne);
    }

    // 9. u_b = Wo @ t_b, c_b
    u_kernel<<<(BGRAPH * HDIM + 255) / 256, 256>>>(targets, Wo, bo);

    // 10. readout
    final_kernel<<<250, 256>>>(regions, Wm, bm, q);
}

// round 12
// speedup vs baseline: 1.1645x; 1.1645x over previous
#include <cuda_runtime.h>
#include <cuda_bf16.h>

#define NNODES 50000
#define FIN    128
#define DDIM   64
#define HDIM   128
#define BGRAPH 16
#define E1N    800000
#define E2N    200000
#define AREG   2000
#define SLOTS  2048
#define BMWORDS 1568

typedef unsigned long long ull;
typedef unsigned int u32;

// ---------------- helpers -------------------------------------------------------
__device__ __forceinline__ ull ffma2(ull a, ull b, ull c) {
    ull d;
    asm("fma.rn.f32x2 %0, %1, %2, %3;" : "=l"(d) : "l"(a), "l"(b), "l"(c));
    return d;
}
__device__ __forceinline__ ull pack2(float lo, float hi) {
    ull r;
    asm("mov.b64 %0, {%1, %2};" : "=l"(r) : "f"(lo), "f"(hi));
    return r;
}
__device__ __forceinline__ void unpack2(ull v, float& lo, float& hi) {
    asm("mov.b64 {%0, %1}, %2;" : "=f"(lo), "=f"(hi) : "l"(v));
}
__device__ __forceinline__ u32 bf2_hi(float a, float b) {
    __nv_bfloat162 h = __floats2bfloat162_rn(a, b);
    return *reinterpret_cast<u32*>(&h);
}
__device__ __forceinline__ u32 bf2_lo(float a, float b) {
    float ra = a - __bfloat162float(__float2bfloat16(a));
    float rb = b - __bfloat162float(__float2bfloat16(b));
    __nv_bfloat162 l = __floats2bfloat162_rn(ra, rb);
    return *reinterpret_cast<u32*>(&l);
}
__device__ __forceinline__ void mma16816(float* c, u32 a0, u32 a1, u32 a2, u32 a3,
                                         u32 b0, u32 b1) {
    asm("mma.sync.aligned.m16n8k16.row.col.f32.bf16.bf16.f32 "
        "{%0,%1,%2,%3}, {%4,%5,%6,%7}, {%8,%9}, {%0,%1,%2,%3};"
        : "+f"(c[0]), "+f"(c[1]), "+f"(c[2]), "+f"(c[3])
        : "r"(a0), "r"(a1), "r"(a2), "r"(a3), "r"(b0), "r"(b1));
}
__device__ __forceinline__ u32 smem_u32(const void* p) {
    u32 a;
    asm("{ .reg .u64 t; cvta.to.shared.u64 t, %1; cvt.u32.u64 %0, t; }"
        : "=r"(a) : "l"(p));
    return a;
}
__device__ __forceinline__ void cpa16(u32 smem_addr, const void* gptr) {
    asm volatile("cp.async.cg.shared.global [%0], [%1], 16;"
                 :: "r"(smem_addr), "l"(gptr) : "memory");
}
__device__ __forceinline__ void cpa16z(u32 smem_addr, const void* gptr, u32 sz) {
    asm volatile("cp.async.cg.shared.global [%0], [%1], 16, %2;"
                 :: "r"(smem_addr), "l"(gptr), "r"(sz) : "memory");
}
#define CP_COMMIT() asm volatile("cp.async.commit_group;" ::: "memory")
#define CP_WAIT0()  asm volatile("cp.async.wait_group 0;" ::: "memory")

// pp permutation for B preconversion (pair jg -> u32 slot)
__host__ __device__ __forceinline__ int pp_of(int jg) {
    return ((jg >> 2) & 1) + (jg & 3) * 2 + (jg >> 3) * 8;
}

// ---------------- scratch -------------------------------------------------------
__device__ __align__(16) float d_yl[NNODES * DDIM];
__device__ __align__(16) float d_yr[NNODES * DDIM];
__device__ __align__(16) float d_agg1[NNODES * DDIM];
__device__ __align__(16) float d_deg1[NNODES];
__device__ __align__(16) float d_gl[NNODES * DDIM];
__device__ __align__(16) float d_gr[NNODES * DDIM];
__device__ __align__(16) int   d_slotmap[BGRAPH * NNODES];
__device__ __align__(16) unsigned d_bitmap[BGRAPH * BMWORDS];
__device__ __align__(16) int   d_counter[BGRAPH];
__device__ __align__(16) float d_acc2[BGRAPH * SLOTS * DDIM];
__device__ __align__(16) float d_deg2[BGRAPH * SLOTS];
__device__ __align__(16) float d_u[BGRAPH * HDIM];
__device__ __align__(16) float d_c[BGRAPH];
// preconverted weights (pair-permuted bf16 split; chunk-major [c][n][24])
__device__ __align__(16) u32 d_B1h[4 * 128 * 24];
__device__ __align__(16) u32 d_B1l[4 * 128 * 24];
__device__ __align__(16) u32 d_B2h[2 * 128 * 24];
__device__ __align__(16) u32 d_B2l[2 * 128 * 24];

// ---------------- clear kernel --------------------------------------------------
static constexpr int CLR_AGG1 = NNODES * DDIM / 4;
static constexpr int CLR_ACC2 = BGRAPH * SLOTS * DDIM / 4;
static constexpr int CLR_SMAP = BGRAPH * NNODES / 4;
static constexpr int CLR_BMAP = BGRAPH * BMWORDS / 4;
static constexpr int CLR_DEG1 = NNODES / 4;
static constexpr int CLR_DEG2 = BGRAPH * SLOTS / 4;
static constexpr int CLR_CNT  = BGRAPH / 4;
static constexpr int CLR_TOTAL = CLR_AGG1 + CLR_ACC2 + CLR_SMAP + CLR_BMAP +
                                 CLR_DEG1 + CLR_DEG2 + CLR_CNT;

__global__ void clear_kernel() {
    int i = blockIdx.x * blockDim.x + threadIdx.x;
    float4 z = make_float4(0.f, 0.f, 0.f, 0.f);
    if (i < CLR_AGG1) { ((float4*)d_agg1)[i] = z; return; }
    i -= CLR_AGG1;
    if (i < CLR_ACC2) { ((float4*)d_acc2)[i] = z; return; }
    i -= CLR_ACC2;
    if (i < CLR_SMAP) { ((int4*)d_slotmap)[i] = make_int4(-1, -1, -1, -1); return; }
    i -= CLR_SMAP;
    if (i < CLR_BMAP) { ((uint4*)d_bitmap)[i] = make_uint4(0, 0, 0, 0); return; }
    i -= CLR_BMAP;
    if (i < CLR_DEG1) { ((float4*)d_deg1)[i] = z; return; }
    i -= CLR_DEG1;
    if (i < CLR_DEG2) { ((float4*)d_deg2)[i] = z; return; }
    i -= CLR_DEG2;
    if (i < CLR_CNT)  { ((int4*)d_counter)[i] = make_int4(0, 0, 0, 0); }
}

// ---------------- weight preconversion ------------------------------------------
__global__ void prep_w_kernel(const float* __restrict__ W1l,
                              const float* __restrict__ W1r,
                              const float* __restrict__ W2l,
                              const float* __restrict__ W2r) {
    int tid = blockIdx.x * blockDim.x + threadIdx.x;
    if (tid >= 768) return;
    if (tid < 512) {
        int c = tid >> 7, n = tid & 127;
        const float* W = (n < 64) ? W1l : W1r;
        int nc = n & 63;
        u32* oh = d_B1h + (c * 128 + n) * 24;
        u32* ol = d_B1l + (c * 128 + n) * 24;
#pragma unroll
        for (int jg = 0; jg < 16; jg++) {
            int k = c * 32 + 2 * jg;
            float wx = W[k * 64 + nc];
            float wy = W[(k + 1) * 64 + nc];
            int pp = pp_of(jg);
            oh[pp] = bf2_hi(wx, wy);
            ol[pp] = bf2_lo(wx, wy);
        }
    } else {
        int id = tid - 512;
        int c = id >> 7, n = id & 127;
        const float* W = (n < 64) ? W2l : W2r;
        int nc = n & 63;
        u32* oh = d_B2h + (c * 128 + n) * 24;
        u32* ol = d_B2l + (c * 128 + n) * 24;
#pragma unroll
        for (int jg = 0; jg < 16; jg++) {
            int k = c * 32 + 2 * jg;
            float wx = W[k * 64 + nc];
            float wy = W[(k + 1) * 64 + nc];
            int pp = pp_of(jg);
            oh[pp] = bf2_hi(wx, wy);
            ol[pp] = bf2_lo(wx, wy);
        }
    }
}

// ================= GEMM1: D[128,128] = x[128rows,128] @ [W1l|W1r] ===============
// cp.async double-buffered; A staged raw f32 (stride 36), converted per-fragment.
// buffer (u32): sAf 4608 | sBh 3072 | sBl 3072 = 10752; x2 buffers = 86016 B.
__global__ __launch_bounds__(256) void mma_gemm1(const float* __restrict__ X,
                                                 const u32* __restrict__ Bgh,
                                                 const u32* __restrict__ Bgl,
                                                 const float* __restrict__ bias,
                                                 float* __restrict__ C1,
                                                 float* __restrict__ C2,
                                                 int nrows) {
    extern __shared__ u32 sm[];
    const int t = threadIdx.x;
    const int w = t >> 5, lane = t & 31;
    const int g = lane >> 2, tg = lane & 3;
    const int row0 = blockIdx.x * 128;

    float acc[16][4];
#pragma unroll
    for (int nt = 0; nt < 16; nt++)
#pragma unroll
        for (int i = 0; i < 4; i++) acc[nt][i] = 0.f;

    auto copy_chunk = [&](int c, int buf) {
        u32 sbase = smem_u32(sm + buf * 10752);
#pragma unroll
        for (int i = 0; i < 4; i++) {           // A: 1024 granules (128 rows x 8)
            int idx = t + i * 256;
            int row = idx >> 3, gc = idx & 7;
            int grow = row0 + row;
            u32 sz = (grow < nrows) ? 16u : 0u;
            const float* src = X + (long)min(grow, nrows - 1) * 128 + c * 32 + gc * 4;
            cpa16z(sbase + (row * 36 + gc * 4) * 4, src, sz);
        }
#pragma unroll
        for (int i = 0; i < 3; i++) {           // B: 768 granules each slab
            int idx = t + i * 256;
            cpa16(sbase + 4608 * 4 + idx * 16, Bgh + c * 3072 + idx * 4);
            cpa16(sbase + 7680 * 4 + idx * 16, Bgl + c * 3072 + idx * 4);
        }
        CP_COMMIT();
    };

    copy_chunk(0, 0);

#pragma unroll
    for (int c = 0; c < 4; c++) {
        CP_WAIT0();
        __syncthreads();
        if (c + 1 < 4) copy_chunk(c + 1, (c + 1) & 1);

        const float* sAf = (const float*)(sm + (c & 1) * 10752);
        const __nv_bfloat16* sBh = (const __nv_bfloat16*)(sm + (c & 1) * 10752 + 4608);
        const __nv_bfloat16* sBl = (const __nv_bfloat16*)(sm + (c & 1) * 10752 + 7680);

#pragma unroll
        for (int ks = 0; ks < 2; ks++) {
            const float* Ar0 = sAf + (w * 16 + g) * 36 + ks * 16 + 2 * tg;
            const float* Ar1 = Ar0 + 8 * 36;
            float2 p00 = *(const float2*)Ar0;
            float2 p02 = *(const float2*)(Ar0 + 8);
            float2 p10 = *(const float2*)Ar1;
            float2 p12 = *(const float2*)(Ar1 + 8);
            u32 h0 = bf2_hi(p00.x, p00.y), h2 = bf2_hi(p02.x, p02.y);
            u32 h1 = bf2_hi(p10.x, p10.y), h3 = bf2_hi(p12.x, p12.y);
            u32 l0 = bf2_lo(p00.x, p00.y), l2 = bf2_lo(p02.x, p02.y);
            u32 l1 = bf2_lo(p10.x, p10.y), l3 = bf2_lo(p12.x, p12.y);
#pragma unroll
            for (int nt = 0; nt < 16; nt++) {
                ull bh = *(const ull*)(sBh + (nt * 8 + g) * 48 + ks * 16 + tg * 4);
                u32 bh0 = (u32)bh, bh1 = (u32)(bh >> 32);
                mma16816(acc[nt], h0, h1, h2, h3, bh0, bh1);
                mma16816(acc[nt], l0, l1, l2, l3, bh0, bh1);
                ull bl = *(const ull*)(sBl + (nt * 8 + g) * 48 + ks * 16 + tg * 4);
                mma16816(acc[nt], h0, h1, h2, h3, (u32)bl, (u32)(bl >> 32));
            }
        }
        __syncthreads();
    }

    int r0 = row0 + w * 16 + g;
#pragma unroll
    for (int nt = 0; nt < 16; nt++) {
        int col = nt * 8 + tg * 2;
        if (col < 64) {
            if (r0 < nrows)
                *(float2*)(C1 + (long)r0 * 64 + col) = make_float2(acc[nt][0], acc[nt][1]);
            if (r0 + 8 < nrows)
                *(float2*)(C1 + (long)(r0 + 8) * 64 + col) = make_float2(acc[nt][2], acc[nt][3]);
        } else {
            int c2 = col - 64;
            float2 bb = *(const float2*)(bias + c2);
            if (r0 < nrows)
                *(float2*)(C2 + (long)r0 * 64 + c2) =
                    make_float2(acc[nt][0] + bb.x, acc[nt][1] + bb.y);
            if (r0 + 8 < nrows)
                *(float2*)(C2 + (long)(r0 + 8) * 64 + c2) =
                    make_float2(acc[nt][2] + bb.x, acc[nt][3] + bb.y);
        }
    }
}

// ================= GEMM2: D = h1 @ [W2l|W2r], h1 fused, all-upfront load =========
// smem (u32): sAgg 8704 | sYr 8704 | sBh 6144 | sBl 6144 | sdeg 128 = 29824 (119296B)
__global__ __launch_bounds__(256) void mma_gemm2(const u32* __restrict__ Bgh,
                                                 const u32* __restrict__ Bgl,
                                                 const float* __restrict__ bias,
                                                 float* __restrict__ C1,
                                                 float* __restrict__ C2,
                                                 int nrows) {
    extern __shared__ u32 sm[];
    const int t = threadIdx.x;
    const int w = t >> 5, lane = t & 31;
    const int g = lane >> 2, tg = lane & 3;
    const int row0 = blockIdx.x * 128;

    float* sAgg = (float*)sm;                    // [128][68]
    float* sYr  = (float*)(sm + 8704);
    float* sdeg = (float*)(sm + 29696);

    {
        u32 sa = smem_u32(sAgg), sy = smem_u32(sYr);
#pragma unroll
        for (int i = 0; i < 8; i++) {            // 2048 granules each (128 x 16)
            int idx = t + i * 256;
            int row = idx >> 4, gc = idx & 15;
            int grow = row0 + row;
            u32 sz = (grow < nrows) ? 16u : 0u;
            long off = (long)min(grow, nrows - 1) * 64 + gc * 4;
            u32 soff = (row * 68 + gc * 4) * 4;
            cpa16z(sa + soff, d_agg1 + off, sz);
            cpa16z(sy + soff, d_yr + off, sz);
        }
        u32 sb = smem_u32(sm + 17408);
#pragma unroll
        for (int i = 0; i < 6; i++) {            // both chunks: 1536 granules/slab
            int idx = t + i * 256;
            cpa16(sb + idx * 16, Bgh + idx * 4);
            cpa16(sb + 6144 * 4 + idx * 16, Bgl + idx * 4);
        }
        CP_COMMIT();
        if (t < 128) {
            int grow = row0 + t;
            float dv = (grow < nrows) ? d_deg1[grow] : 1.f;
            sdeg[t] = 1.f / fmaxf(dv, 1.f);
        }
        CP_WAIT0();
        __syncthreads();
    }

    float acc[16][4];
#pragma unroll
    for (int nt = 0; nt < 16; nt++)
#pragma unroll
        for (int i = 0; i < 4; i++) acc[nt][i] = 0.f;

    const float inv0 = sdeg[w * 16 + g];
    const float inv1 = sdeg[w * 16 + g + 8];

#pragma unroll
    for (int c = 0; c < 2; c++) {
        const __nv_bfloat16* sBh = (const __nv_bfloat16*)(sm + 17408 + c * 3072);
        const __nv_bfloat16* sBl = (const __nv_bfloat16*)(sm + 23552 + c * 3072);
#pragma unroll
        for (int ks = 0; ks < 2; ks++) {
            int kb = c * 32 + ks * 16 + 2 * tg;
            int r0i = (w * 16 + g) * 68, r1i = r0i + 8 * 68;
            float2 a00 = *(const float2*)(sAgg + r0i + kb);
            float2 a02 = *(const float2*)(sAgg + r0i + kb + 8);
            float2 a10 = *(const float2*)(sAgg + r1i + kb);
            float2 a12 = *(const float2*)(sAgg + r1i + kb + 8);
            float2 y00 = *(const float2*)(sYr + r0i + kb);
            float2 y02 = *(const float2*)(sYr + r0i + kb + 8);
            float2 y10 = *(const float2*)(sYr + r1i + kb);
            float2 y12 = *(const float2*)(sYr + r1i + kb + 8);
            float v00x = fmaxf(a00.x * inv0 + y00.x, 0.f);
            float v00y = fmaxf(a00.y * inv0 + y00.y, 0.f);
            float v02x = fmaxf(a02.x * inv0 + y02.x, 0.f);
            float v02y = fmaxf(a02.y * inv0 + y02.y, 0.f);
            float v10x = fmaxf(a10.x * inv1 + y10.x, 0.f);
            float v10y = fmaxf(a10.y * inv1 + y10.y, 0.f);
            float v12x = fmaxf(a12.x * inv1 + y12.x, 0.f);
            float v12y = fmaxf(a12.y * inv1 + y12.y, 0.f);
            u32 h0 = bf2_hi(v00x, v00y), h2 = bf2_hi(v02x, v02y);
            u32 h1 = bf2_hi(v10x, v10y), h3 = bf2_hi(v12x, v12y);
            u32 l0 = bf2_lo(v00x, v00y), l2 = bf2_lo(v02x, v02y);
            u32 l1 = bf2_lo(v10x, v10y), l3 = bf2_lo(v12x, v12y);
#pragma unroll
            for (int nt = 0; nt < 16; nt++) {
                ull bh = *(const ull*)(sBh + (nt * 8 + g) * 48 + ks * 16 + tg * 4);
                u32 bh0 = (u32)bh, bh1 = (u32)(bh >> 32);
                mma16816(acc[nt], h0, h1, h2, h3, bh0, bh1);
                mma16816(acc[nt], l0, l1, l2, l3, bh0, bh1);
                ull bl = *(const ull*)(sBl + (nt * 8 + g) * 48 + ks * 16 + tg * 4);
                mma16816(acc[nt], h0, h1, h2, h3, (u32)bl, (u32)(bl >> 32));
            }
        }
    }

    int r0 = row0 + w * 16 + g;
#pragma unroll
    for (int nt = 0; nt < 16; nt++) {
        int col = nt * 8 + tg * 2;
        if (col < 64) {
            if (r0 < nrows)
                *(float2*)(C1 + (long)r0 * 64 + col) = make_float2(acc[nt][0], acc[nt][1]);
            if (r0 + 8 < nrows)
                *(float2*)(C1 + (long)(r0 + 8) * 64 + col) = make_float2(acc[nt][2], acc[nt][3]);
        } else {
            int c2 = col - 64;
            float2 bb = *(const float2*)(bias + c2);
            if (r0 < nrows)
                *(float2*)(C2 + (long)r0 * 64 + c2) =
                    make_float2(acc[nt][0] + bb.x, acc[nt][1] + bb.y);
            if (r0 + 8 < nrows)
                *(float2*)(C2 + (long)(r0 + 8) * 64 + c2) =
                    make_float2(acc[nt][2] + bb.x, acc[nt][3] + bb.y);
        }
    }
}

// ---------------- conv1 edge scatter (8 edges/warp) -----------------------------
__global__ void scatter1_kernel(const int* __restrict__ ei) {
    int tid = blockIdx.x * blockDim.x + threadIdx.x;
    int w = tid >> 5, lane = tid & 31;
    int e0 = 8 * w + (lane >> 4);
    int j = lane & 15;

    int s0 = ei[e0];
    int s1 = ei[e0 + 2];
    int s2 = ei[e0 + 4];
    int s3 = ei[e0 + 6];
    int dd0 = ei[E1N + e0];
    int dd1 = ei[E1N + e0 + 2];
    int dd2 = ei[E1N + e0 + 4];
    int dd3 = ei[E1N + e0 + 6];

    float4 v0 = ((const float4*)(d_yl + s0 * 64))[j];
    float4 v1 = ((const float4*)(d_yl + s1 * 64))[j];
    float4 v2 = ((const float4*)(d_yl + s2 * 64))[j];
    float4 v3 = ((const float4*)(d_yl + s3 * 64))[j];

    float* p0 = d_agg1 + dd0 * 64 + 4 * j;
    float* p1 = d_agg1 + dd1 * 64 + 4 * j;
    float* p2 = d_agg1 + dd2 * 64 + 4 * j;
    float* p3 = d_agg1 + dd3 * 64 + 4 * j;
    asm volatile("red.global.add.v4.f32 [%0], {%1,%2,%3,%4};"
                 :: "l"(p0), "f"(v0.x), "f"(v0.y), "f"(v0.z), "f"(v0.w) : "memory");
    asm volatile("red.global.add.v4.f32 [%0], {%1,%2,%3,%4};"
                 :: "l"(p1), "f"(v1.x), "f"(v1.y), "f"(v1.z), "f"(v1.w) : "memory");
    asm volatile("red.global.add.v4.f32 [%0], {%1,%2,%3,%4};"
                 :: "l"(p2), "f"(v2.x), "f"(v2.y), "f"(v2.z), "f"(v2.w) : "memory");
    asm volatile("red.global.add.v4.f32 [%0], {%1,%2,%3,%4};"
                 :: "l"(p3), "f"(v3.x), "f"(v3.y), "f"(v3.z), "f"(v3.w) : "memory");
    if (j == 0) {
        atomicAdd(&d_deg1[dd0], 1.0f);
        atomicAdd(&d_deg1[dd1], 1.0f);
        atomicAdd(&d_deg1[dd2], 1.0f);
        atomicAdd(&d_deg1[dd3], 1.0f);
    }
}

// ---------------- slot assignment + bitmap --------------------------------------
__global__ void slot_kernel(const int* __restrict__ targets,
                            const int* __restrict__ regions) {
    int idx = blockIdx.x * blockDim.x + threadIdx.x;
    if (idx >= BGRAPH * (AREG + 1)) return;
    int b = idx / (AREG + 1);
    int j = idx % (AREG + 1);
    int node = (j == AREG) ? targets[b] : regions[b * AREG + j];
    atomicOr(&d_bitmap[b * BMWORDS + (node >> 5)], 1u << (node & 31));
    int* p = &d_slotmap[b * NNODES + node];
    if (atomicCAS(p, -1, -2) == -1) {
        int s = atomicAdd(&d_counter[b], 1);
        atomicExch(p, s);
    }
}

// ---------------- conv2 scatter with smem bitmap filter -------------------------
__global__ void scatter2_kernel(const int* __restrict__ ne) {
    __shared__ unsigned sbm[BMWORDS];
    const int b = blockIdx.y;
    for (int i = threadIdx.x; i < BMWORDS; i += 320)
        sbm[i] = d_bitmap[b * BMWORDS + i];
    __syncthreads();

    const int lane = threadIdx.x & 31;
    const long base = (long)b * 2 * E2N;
    int e0 = blockIdx.x * 1600 + threadIdx.x;
#pragma unroll
    for (int it = 0; it < 5; it++) {
        int e = e0 + it * 320;
        int dst = ne[base + E2N + e];
        bool hit = (sbm[dst >> 5] >> (dst & 31)) & 1u;
        int slot = -1, src = 0;
        if (hit) {
            slot = d_slotmap[b * NNODES + dst];
            src = ne[base + e];
        }
        unsigned mask = __ballot_sync(0xffffffffu, hit);
        while (mask) {
            int bit = __ffs(mask) - 1;
            mask &= mask - 1;
            int es = __shfl_sync(0xffffffffu, src, bit);
            int sl = __shfl_sync(0xffffffffu, slot, bit);
            float2 v = ((const float2*)(d_gl + es * 64))[lane];
            float* p = d_acc2 + (b * SLOTS + sl) * 64 + 2 * lane;
            asm volatile("red.global.add.v2.f32 [%0], {%1,%2};"
                         :: "l"(p), "f"(v.x), "f"(v.y) : "memory");
            if (lane == 0) atomicAdd(&d_deg2[b * SLOTS + sl], 1.0f);
        }
    }
}

// ---------------- u_b = Wo @ t_b , c_b = bo . t_b -------------------------------
__global__ void u_kernel(const int* __restrict__ targets,
                         const float* __restrict__ Wo,
                         const float* __restrict__ bo) {
    int idx = blockIdx.x * blockDim.x + threadIdx.x;
    if (idx >= BGRAPH * HDIM) return;
    int b = idx >> 7;
    int h = idx & 127;
    int node = targets[b];
    int s = d_slotmap[b * NNODES + node];
    int base = (b * SLOTS + s) * 64;
    float inv = 1.f / fmaxf(d_deg2[b * SLOTS + s], 1.f);
    float acc = 0.f, c = 0.f;
#pragma unroll
    for (int d = 0; d < 64; d++) {
        float td = fmaxf(d_acc2[base + d] * inv + d_gr[node * 64 + d], 0.f);
        acc += Wo[h * 64 + d] * td;
        c += bo[d] * td;
    }
    d_u[idx] = acc;
    if (h == 0) d_c[b] = c;
}

// ---------------- final readout -------------------------------------------------
__global__ void final_kernel(const int* __restrict__ regions,
                             const float* __restrict__ Wm,
                             const float* __restrict__ bm,
                             float* __restrict__ q) {
    __shared__ float sWm[64 * 128];
    __shared__ float sreg[8][8][64];
    for (int i = threadIdx.x; i < 64 * 128; i += blockDim.x)
        sWm[i] = Wm[i];
    __syncthreads();

    const int lane = threadIdx.x & 31;
    const int wl = threadIdx.x >> 5;
    const float2 bmp0 = ((const float2*)bm)[lane];
    const float2 bmp1 = ((const float2*)bm)[lane + 32];

    for (int tile = blockIdx.x * 8 + wl; tile < 4000; tile += gridDim.x * 8) {
        int b = tile / 250;
#pragma unroll
        for (int r = 0; r < 8; r++) {
            int p = tile * 8 + r;
            int node = regions[p];
            int s = d_slotmap[b * NNODES + node];
            int base = (b * SLOTS + s) * 64;
            float inv = 1.f / fmaxf(d_deg2[b * SLOTS + s], 1.f);
            float2 a = ((const float2*)(d_acc2 + base))[lane];
            float2 g = ((const float2*)(d_gr + node * 64))[lane];
            sreg[wl][r][2 * lane]     = fmaxf(a.x * inv + g.x, 0.f);
            sreg[wl][r][2 * lane + 1] = fmaxf(a.y * inv + g.y, 0.f);
        }
        __syncwarp();

        ull acc0[8], acc1[8];
#pragma unroll
        for (int r = 0; r < 8; r++) { acc0[r] = 0ull; acc1[r] = 0ull; }

#pragma unroll 8
        for (int d = 0; d < 64; d++) {
            ull w0 = ((const ull*)(sWm + d * 128))[lane];
            ull w1 = ((const ull*)(sWm + d * 128 + 64))[lane];
#pragma unroll
            for (int r = 0; r < 8; r++) {
                float rd = sreg[wl][r][d];
                ull rdp = pack2(rd, rd);
                acc0[r] = ffma2(rdp, w0, acc0[r]);
                acc1[r] = ffma2(rdp, w1, acc1[r]);
            }
        }

        const float2* ubp = (const float2*)(d_u + b * HDIM);
        float2 u0 = ubp[lane];
        float2 u1 = ubp[lane + 32];
        float cb = d_c[b];
#pragma unroll
        for (int r = 0; r < 8; r++) {
            float m0, m1, m2, m3;
            unpack2(acc0[r], m0, m1);
            unpack2(acc1[r], m2, m3);
            float sum = fmaxf(m0 + bmp0.x, 0.f) * u0.x
                      + fmaxf(m1 + bmp0.y, 0.f) * u0.y
                      + fmaxf(m2 + bmp1.x, 0.f) * u1.x
                      + fmaxf(m3 + bmp1.y, 0.f) * u1.y;
#pragma unroll
            for (int o = 16; o > 0; o >>= 1)
                sum += __shfl_down_sync(0xffffffffu, sum, o);
            if (lane == 0) q[tile * 8 + r] = sum + cb;
        }
        __syncwarp();
    }
}

// ---------------- launch ---------------------------------------------------------
extern "C" void kernel_launch(void* const* d_in, const int* in_sizes, int n_in,
                              void* d_out, int out_size) {
    const float* x       = (const float*)d_in[0];
    const int*   ei      = (const int*)  d_in[1];
    const int*   ne      = (const int*)  d_in[2];
    const int*   targets = (const int*)  d_in[3];
    const int*   regions = (const int*)  d_in[4];
    const float* W1l     = (const float*)d_in[5];
    const float* W1r     = (const float*)d_in[6];
    const float* b1      = (const float*)d_in[7];
    const float* W2l     = (const float*)d_in[8];
    const float* W2r     = (const float*)d_in[9];
    const float* b2      = (const float*)d_in[10];
    const float* Wm      = (const float*)d_in[11];
    const float* bm      = (const float*)d_in[12];
    const float* Wo      = (const float*)d_in[13];
    const float* bo      = (const float*)d_in[14];
    float* q = (float*)d_out;

    float *p_yl, *p_yr, *p_gl, *p_gr;
    u32 *p_B1h, *p_B1l, *p_B2h, *p_B2l;
    cudaGetSymbolAddress((void**)&p_yl, d_yl);
    cudaGetSymbolAddress((void**)&p_yr, d_yr);
    cudaGetSymbolAddress((void**)&p_gl, d_gl);
    cudaGetSymbolAddress((void**)&p_gr, d_gr);
    cudaGetSymbolAddress((void**)&p_B1h, d_B1h);
    cudaGetSymbolAddress((void**)&p_B1l, d_B1l);
    cudaGetSymbolAddress((void**)&p_B2h, d_B2h);
    cudaGetSymbolAddress((void**)&p_B2l, d_B2l);

    cudaFuncSetAttribute(mma_gemm1, cudaFuncAttributeMaxDynamicSharedMemorySize, 86016);
    cudaFuncSetAttribute(mma_gemm2, cudaFuncAttributeMaxDynamicSharedMemorySize, 119296);

    // 0. clear scratch
    clear_kernel<<<(CLR_TOTAL + 255) / 256, 256>>>();

    // 1. weight preconversion
    prep_w_kernel<<<3, 256>>>(W1l, W1r, W2l, W2r);

    // 2. slot assignment + bitmap (independent; needs clear)
    slot_kernel<<<(BGRAPH * (AREG + 1) + 255) / 256, 256>>>(targets, regions);

    // 3. GEMM1: yl = x@W1l ; yr = x@W1r + b1   <-- profiled slot
    mma_gemm1<<<391, 256, 86016>>>(x, p_B1h, p_B1l, b1, p_yl, p_yr, NNODES);

    // 4. conv1 scatter
    {
        int warps = E1N / 8;
        int blocks = (warps * 32 + 255) / 256;
        scatter1_kernel<<<blocks, 256>>>(ei);
    }

    // 5. GEMM2: gl = h1@W2l ; gr = h1@W2r + b2 (h1 fused, all-upfront load)
    mma_gemm2<<<391, 256, 119296>>>(p_B2h, p_B2l, b2, p_gl, p_gr, NNODES);

    // 6. conv2 scatter with smem bitmap filter
    {
        dim3 grid(125, BGRAPH);
        scatter2_kernel<<<grid, 320>>>(ne);
    }

    // 7. u_b = Wo @ t_b, c_b
    u_kernel<<<(BGRAPH * HDIM + 255) / 256, 256>>>(targets, Wo, bo);

    // 8. readout
    final_kernel<<<250, 256>>>(regions, Wm, bm, q);
}

// round 13
// speedup vs baseline: 1.2573x; 1.0797x over previous
#include <cuda_runtime.h>
#include <cuda_bf16.h>

#define NNODES 50000
#define FIN    128
#define DDIM   64
#define HDIM   128
#define BGRAPH 16
#define E1N    800000
#define E2N    200000
#define AREG   2000
#define SLOTS  2048
#define BMWORDS 1568
#define DEGCAP 96

typedef unsigned long long ull;
typedef unsigned int u32;

// ---------------- helpers -------------------------------------------------------
__device__ __forceinline__ ull ffma2(ull a, ull b, ull c) {
    ull d;
    asm("fma.rn.f32x2 %0, %1, %2, %3;" : "=l"(d) : "l"(a), "l"(b), "l"(c));
    return d;
}
__device__ __forceinline__ ull pack2(float lo, float hi) {
    ull r;
    asm("mov.b64 %0, {%1, %2};" : "=l"(r) : "f"(lo), "f"(hi));
    return r;
}
__device__ __forceinline__ void unpack2(ull v, float& lo, float& hi) {
    asm("mov.b64 {%0, %1}, %2;" : "=f"(lo), "=f"(hi) : "l"(v));
}
__device__ __forceinline__ u32 bf2_hi(float a, float b) {
    __nv_bfloat162 h = __floats2bfloat162_rn(a, b);
    return *reinterpret_cast<u32*>(&h);
}
__device__ __forceinline__ u32 bf2_lo(float a, float b) {
    float ra = a - __bfloat162float(__float2bfloat16(a));
    float rb = b - __bfloat162float(__float2bfloat16(b));
    __nv_bfloat162 l = __floats2bfloat162_rn(ra, rb);
    return *reinterpret_cast<u32*>(&l);
}
__device__ __forceinline__ void mma16816(float* c, u32 a0, u32 a1, u32 a2, u32 a3,
                                         u32 b0, u32 b1) {
    asm("mma.sync.aligned.m16n8k16.row.col.f32.bf16.bf16.f32 "
        "{%0,%1,%2,%3}, {%4,%5,%6,%7}, {%8,%9}, {%0,%1,%2,%3};"
        : "+f"(c[0]), "+f"(c[1]), "+f"(c[2]), "+f"(c[3])
        : "r"(a0), "r"(a1), "r"(a2), "r"(a3), "r"(b0), "r"(b1));
}
__device__ __forceinline__ u32 smem_u32(const void* p) {
    u32 a;
    asm("{ .reg .u64 t; cvta.to.shared.u64 t, %1; cvt.u32.u64 %0, t; }"
        : "=r"(a) : "l"(p));
    return a;
}
__device__ __forceinline__ void cpa16(u32 smem_addr, const void* gptr) {
    asm volatile("cp.async.cg.shared.global [%0], [%1], 16;"
                 :: "r"(smem_addr), "l"(gptr) : "memory");
}
__device__ __forceinline__ void cpa16z(u32 smem_addr, const void* gptr, u32 sz) {
    asm volatile("cp.async.cg.shared.global [%0], [%1], 16, %2;"
                 :: "r"(smem_addr), "l"(gptr), "r"(sz) : "memory");
}
#define CP_COMMIT() asm volatile("cp.async.commit_group;" ::: "memory")
#define CP_WAIT0()  asm volatile("cp.async.wait_group 0;" ::: "memory")

__host__ __device__ __forceinline__ int pp_of(int jg) {
    return ((jg >> 2) & 1) + (jg & 3) * 2 + (jg >> 3) * 8;
}

// ---------------- scratch -------------------------------------------------------
__device__ __align__(16) float d_yl[NNODES * DDIM];
__device__ __align__(16) float d_yr[NNODES * DDIM];
__device__ __align__(16) float d_h1[NNODES * DDIM];
__device__ __align__(16) int   d_cnt[NNODES];
__device__ __align__(16) int   d_csr[NNODES * DEGCAP];
__device__ __align__(16) float d_gl[NNODES * DDIM];
__device__ __align__(16) float d_gr[NNODES * DDIM];
__device__ __align__(16) int   d_slotmap[BGRAPH * NNODES];
__device__ __align__(16) unsigned d_bitmap[BGRAPH * BMWORDS];
__device__ __align__(16) int   d_counter[BGRAPH];
__device__ __align__(16) float d_acc2[BGRAPH * SLOTS * DDIM];
__device__ __align__(16) float d_deg2[BGRAPH * SLOTS];
__device__ __align__(16) float d_u[BGRAPH * HDIM];
__device__ __align__(16) float d_c[BGRAPH];
// preconverted weights (pair-permuted bf16 split; chunk-major [c][n][24])
__device__ __align__(16) u32 d_B1h[4 * 128 * 24];
__device__ __align__(16) u32 d_B1l[4 * 128 * 24];
__device__ __align__(16) u32 d_B2h[2 * 128 * 24];
__device__ __align__(16) u32 d_B2l[2 * 128 * 24];

// ---------------- clear kernel (acc2/slotmap/bitmap/deg2/counter) ---------------
static constexpr int CLR_ACC2 = BGRAPH * SLOTS * DDIM / 4;
static constexpr int CLR_SMAP = BGRAPH * NNODES / 4;
static constexpr int CLR_BMAP = BGRAPH * BMWORDS / 4;
static constexpr int CLR_DEG2 = BGRAPH * SLOTS / 4;
static constexpr int CLR_CNT  = BGRAPH / 4;
static constexpr int CLR_TOTAL = CLR_ACC2 + CLR_SMAP + CLR_BMAP + CLR_DEG2 + CLR_CNT;

__global__ void clear_kernel() {
    int i = blockIdx.x * blockDim.x + threadIdx.x;
    float4 z = make_float4(0.f, 0.f, 0.f, 0.f);
    if (i < CLR_ACC2) { ((float4*)d_acc2)[i] = z; return; }
    i -= CLR_ACC2;
    if (i < CLR_SMAP) { ((int4*)d_slotmap)[i] = make_int4(-1, -1, -1, -1); return; }
    i -= CLR_SMAP;
    if (i < CLR_BMAP) { ((uint4*)d_bitmap)[i] = make_uint4(0, 0, 0, 0); return; }
    i -= CLR_BMAP;
    if (i < CLR_DEG2) { ((float4*)d_deg2)[i] = z; return; }
    i -= CLR_DEG2;
    if (i < CLR_CNT)  { ((int4*)d_counter)[i] = make_int4(0, 0, 0, 0); }
}

// ---------------- weight preconversion + cnt clear ------------------------------
__global__ void prep_w_kernel(const float* __restrict__ W1l,
                              const float* __restrict__ W1r,
                              const float* __restrict__ W2l,
                              const float* __restrict__ W2r) {
    int tid = blockIdx.x * blockDim.x + threadIdx.x;
    if (tid < 512) {
        int c = tid >> 7, n = tid & 127;
        const float* W = (n < 64) ? W1l : W1r;
        int nc = n & 63;
        u32* oh = d_B1h + (c * 128 + n) * 24;
        u32* ol = d_B1l + (c * 128 + n) * 24;
#pragma unroll
        for (int jg = 0; jg < 16; jg++) {
            int k = c * 32 + 2 * jg;
            float wx = W[k * 64 + nc];
            float wy = W[(k + 1) * 64 + nc];
            int pp = pp_of(jg);
            oh[pp] = bf2_hi(wx, wy);
            ol[pp] = bf2_lo(wx, wy);
        }
    } else if (tid < 768) {
        int id = tid - 512;
        int c = id >> 7, n = id & 127;
        const float* W = (n < 64) ? W2l : W2r;
        int nc = n & 63;
        u32* oh = d_B2h + (c * 128 + n) * 24;
        u32* ol = d_B2l + (c * 128 + n) * 24;
#pragma unroll
        for (int jg = 0; jg < 16; jg++) {
            int k = c * 32 + 2 * jg;
            float wx = W[k * 64 + nc];
            float wy = W[(k + 1) * 64 + nc];
            int pp = pp_of(jg);
            oh[pp] = bf2_hi(wx, wy);
            ol[pp] = bf2_lo(wx, wy);
        }
    } else {
        int id = tid - 768;                // clear d_cnt: 12500 int4
        if (id < NNODES / 4)
            ((int4*)d_cnt)[id] = make_int4(0, 0, 0, 0);
    }
}

// ---------------- conv1 bucket fill: csr[dst*96 + slot] = src -------------------
__global__ void fill_kernel(const int* __restrict__ ei) {
    int idx = (blockIdx.x * blockDim.x + threadIdx.x) * 4;
    if (idx >= E1N) return;
    int4 s = *(const int4*)(ei + idx);
    int4 d = *(const int4*)(ei + E1N + idx);
    int o0 = atomicAdd(&d_cnt[d.x], 1);
    int o1 = atomicAdd(&d_cnt[d.y], 1);
    int o2 = atomicAdd(&d_cnt[d.z], 1);
    int o3 = atomicAdd(&d_cnt[d.w], 1);
    d_csr[d.x * DEGCAP + o0] = s.x;
    d_csr[d.y * DEGCAP + o1] = s.y;
    d_csr[d.z * DEGCAP + o2] = s.z;
    d_csr[d.w * DEGCAP + o3] = s.w;
}

// ---------------- conv1 gather: h1 = relu(mean_{src} yl[src] + yr) --------------
// half-warp (16 lanes) per node; 8-deep unroll for MLP.
__global__ void gather1_kernel() {
    int tid = blockIdx.x * blockDim.x + threadIdx.x;
    int w = tid >> 5, lane = tid & 31;
    int node = 2 * w + (lane >> 4);
    int j = lane & 15;
    int deg = d_cnt[node];
    const int* csr = d_csr + node * DEGCAP;
    float4 acc = make_float4(0.f, 0.f, 0.f, 0.f);
    int i = 0;
    for (; i + 8 <= deg; i += 8) {
        int s0 = __ldg(csr + i);
        int s1 = __ldg(csr + i + 1);
        int s2 = __ldg(csr + i + 2);
        int s3 = __ldg(csr + i + 3);
        int s4 = __ldg(csr + i + 4);
        int s5 = __ldg(csr + i + 5);
        int s6 = __ldg(csr + i + 6);
        int s7 = __ldg(csr + i + 7);
        float4 v0 = ((const float4*)(d_yl + s0 * 64))[j];
        float4 v1 = ((const float4*)(d_yl + s1 * 64))[j];
        float4 v2 = ((const float4*)(d_yl + s2 * 64))[j];
        float4 v3 = ((const float4*)(d_yl + s3 * 64))[j];
        float4 v4 = ((const float4*)(d_yl + s4 * 64))[j];
        float4 v5 = ((const float4*)(d_yl + s5 * 64))[j];
        float4 v6 = ((const float4*)(d_yl + s6 * 64))[j];
        float4 v7 = ((const float4*)(d_yl + s7 * 64))[j];
        acc.x += (v0.x + v1.x) + (v2.x + v3.x) + ((v4.x + v5.x) + (v6.x + v7.x));
        acc.y += (v0.y + v1.y) + (v2.y + v3.y) + ((v4.y + v5.y) + (v6.y + v7.y));
        acc.z += (v0.z + v1.z) + (v2.z + v3.z) + ((v4.z + v5.z) + (v6.z + v7.z));
        acc.w += (v0.w + v1.w) + (v2.w + v3.w) + ((v4.w + v5.w) + (v6.w + v7.w));
    }
    for (; i < deg; i++) {
        int s = __ldg(csr + i);
        float4 v = ((const float4*)(d_yl + s * 64))[j];
        acc.x += v.x; acc.y += v.y; acc.z += v.z; acc.w += v.w;
    }
    float inv = 1.f / fmaxf((float)deg, 1.f);
    float4 y = ((const float4*)(d_yr + node * 64))[j];
    float4 h;
    h.x = fmaxf(acc.x * inv + y.x, 0.f);
    h.y = fmaxf(acc.y * inv + y.y, 0.f);
    h.z = fmaxf(acc.z * inv + y.z, 0.f);
    h.w = fmaxf(acc.w * inv + y.w, 0.f);
    ((float4*)(d_h1 + node * 64))[j] = h;
}

// ================= GEMM1: D[128,128] = x @ [W1l|W1r], cp.async 2-buffer =========
__global__ __launch_bounds__(256) void mma_gemm1(const float* __restrict__ X,
                                                 const u32* __restrict__ Bgh,
                                                 const u32* __restrict__ Bgl,
                                                 const float* __restrict__ bias,
                                                 float* __restrict__ C1,
                                                 float* __restrict__ C2,
                                                 int nrows) {
    extern __shared__ u32 sm[];
    const int t = threadIdx.x;
    const int w = t >> 5, lane = t & 31;
    const int g = lane >> 2, tg = lane & 3;
    const int row0 = blockIdx.x * 128;

    float acc[16][4];
#pragma unroll
    for (int nt = 0; nt < 16; nt++)
#pragma unroll
        for (int i = 0; i < 4; i++) acc[nt][i] = 0.f;

    auto copy_chunk = [&](int c, int buf) {
        u32 sbase = smem_u32(sm + buf * 10752);
#pragma unroll
        for (int i = 0; i < 4; i++) {
            int idx = t + i * 256;
            int row = idx >> 3, gc = idx & 7;
            int grow = row0 + row;
            u32 sz = (grow < nrows) ? 16u : 0u;
            const float* src = X + (long)min(grow, nrows - 1) * 128 + c * 32 + gc * 4;
            cpa16z(sbase + (row * 36 + gc * 4) * 4, src, sz);
        }
#pragma unroll
        for (int i = 0; i < 3; i++) {
            int idx = t + i * 256;
            cpa16(sbase + 4608 * 4 + idx * 16, Bgh + c * 3072 + idx * 4);
            cpa16(sbase + 7680 * 4 + idx * 16, Bgl + c * 3072 + idx * 4);
        }
        CP_COMMIT();
    };

    copy_chunk(0, 0);

#pragma unroll
    for (int c = 0; c < 4; c++) {
        CP_WAIT0();
        __syncthreads();
        if (c + 1 < 4) copy_chunk(c + 1, (c + 1) & 1);

        const float* sAf = (const float*)(sm + (c & 1) * 10752);
        const __nv_bfloat16* sBh = (const __nv_bfloat16*)(sm + (c & 1) * 10752 + 4608);
        const __nv_bfloat16* sBl = (const __nv_bfloat16*)(sm + (c & 1) * 10752 + 7680);

#pragma unroll
        for (int ks = 0; ks < 2; ks++) {
            const float* Ar0 = sAf + (w * 16 + g) * 36 + ks * 16 + 2 * tg;
            const float* Ar1 = Ar0 + 8 * 36;
            float2 p00 = *(const float2*)Ar0;
            float2 p02 = *(const float2*)(Ar0 + 8);
            float2 p10 = *(const float2*)Ar1;
            float2 p12 = *(const float2*)(Ar1 + 8);
            u32 h0 = bf2_hi(p00.x, p00.y), h2 = bf2_hi(p02.x, p02.y);
            u32 h1 = bf2_hi(p10.x, p10.y), h3 = bf2_hi(p12.x, p12.y);
            u32 l0 = bf2_lo(p00.x, p00.y), l2 = bf2_lo(p02.x, p02.y);
            u32 l1 = bf2_lo(p10.x, p10.y), l3 = bf2_lo(p12.x, p12.y);
#pragma unroll
            for (int nt = 0; nt < 16; nt++) {
                ull bh = *(const ull*)(sBh + (nt * 8 + g) * 48 + ks * 16 + tg * 4);
                u32 bh0 = (u32)bh, bh1 = (u32)(bh >> 32);
                mma16816(acc[nt], h0, h1, h2, h3, bh0, bh1);
                mma16816(acc[nt], l0, l1, l2, l3, bh0, bh1);
                ull bl = *(const ull*)(sBl + (nt * 8 + g) * 48 + ks * 16 + tg * 4);
                mma16816(acc[nt], h0, h1, h2, h3, (u32)bl, (u32)(bl >> 32));
            }
        }
        __syncthreads();
    }

    int r0 = row0 + w * 16 + g;
#pragma unroll
    for (int nt = 0; nt < 16; nt++) {
        int col = nt * 8 + tg * 2;
        if (col < 64) {
            if (r0 < nrows)
                *(float2*)(C1 + (long)r0 * 64 + col) = make_float2(acc[nt][0], acc[nt][1]);
            if (r0 + 8 < nrows)
                *(float2*)(C1 + (long)(r0 + 8) * 64 + col) = make_float2(acc[nt][2], acc[nt][3]);
        } else {
            int c2 = col - 64;
            float2 bb = *(const float2*)(bias + c2);
            if (r0 < nrows)
                *(float2*)(C2 + (long)r0 * 64 + c2) =
                    make_float2(acc[nt][0] + bb.x, acc[nt][1] + bb.y);
            if (r0 + 8 < nrows)
                *(float2*)(C2 + (long)(r0 + 8) * 64 + c2) =
                    make_float2(acc[nt][2] + bb.x, acc[nt][3] + bb.y);
        }
    }
}

// ================= GEMM2: D = h1 @ [W2l|W2r], single upfront load ===============
// smem (u32): sH 128*68=8704 | sBh 6144 | sBl 6144 = 20992 u32 (83968 B)
__global__ __launch_bounds__(256) void mma_gemm2(const u32* __restrict__ Bgh,
                                                 const u32* __restrict__ Bgl,
                                                 const float* __restrict__ bias,
                                                 float* __restrict__ C1,
                                                 float* __restrict__ C2,
                                                 int nrows) {
    extern __shared__ u32 sm[];
    const int t = threadIdx.x;
    const int w = t >> 5, lane = t & 31;
    const int g = lane >> 2, tg = lane & 3;
    const int row0 = blockIdx.x * 128;

    {
        u32 sh = smem_u32(sm);
#pragma unroll
        for (int i = 0; i < 8; i++) {           // h1: 2048 granules (128 x 16)
            int idx = t + i * 256;
            int row = idx >> 4, gc = idx & 15;
            int grow = row0 + row;
            u32 sz = (grow < nrows) ? 16u : 0u;
            cpa16z(sh + (row * 68 + gc * 4) * 4,
                   d_h1 + (long)min(grow, nrows - 1) * 64 + gc * 4, sz);
        }
        u32 sb = smem_u32(sm + 8704);
#pragma unroll
        for (int i = 0; i < 6; i++) {           // both B chunks, both slabs
            int idx = t + i * 256;
            cpa16(sb + idx * 16, Bgh + idx * 4);
            cpa16(sb + 6144 * 4 + idx * 16, Bgl + idx * 4);
        }
        CP_COMMIT();
        CP_WAIT0();
        __syncthreads();
    }

    float acc[16][4];
#pragma unroll
    for (int nt = 0; nt < 16; nt++)
#pragma unroll
        for (int i = 0; i < 4; i++) acc[nt][i] = 0.f;

    const float* sH = (const float*)sm;

#pragma unroll
    for (int c = 0; c < 2; c++) {
        const __nv_bfloat16* sBh = (const __nv_bfloat16*)(sm + 8704 + c * 3072);
        const __nv_bfloat16* sBl = (const __nv_bfloat16*)(sm + 14848 + c * 3072);
#pragma unroll
        for (int ks = 0; ks < 2; ks++) {
            const float* Ar0 = sH + (w * 16 + g) * 68 + c * 32 + ks * 16 + 2 * tg;
            const float* Ar1 = Ar0 + 8 * 68;
            float2 p00 = *(const float2*)Ar0;
            float2 p02 = *(const float2*)(Ar0 + 8);
            float2 p10 = *(const float2*)Ar1;
            float2 p12 = *(const float2*)(Ar1 + 8);
            u32 h0 = bf2_hi(p00.x, p00.y), h2 = bf2_hi(p02.x, p02.y);
            u32 h1 = bf2_hi(p10.x, p10.y), h3 = bf2_hi(p12.x, p12.y);
            u32 l0 = bf2_lo(p00.x, p00.y), l2 = bf2_lo(p02.x, p02.y);
            u32 l1 = bf2_lo(p10.x, p10.y), l3 = bf2_lo(p12.x, p12.y);
#pragma unroll
            for (int nt = 0; nt < 16; nt++) {
                ull bh = *(const ull*)(sBh + (nt * 8 + g) * 48 + ks * 16 + tg * 4);
                u32 bh0 = (u32)bh, bh1 = (u32)(bh >> 32);
                mma16816(acc[nt], h0, h1, h2, h3, bh0, bh1);
                mma16816(acc[nt], l0, l1, l2, l3, bh0, bh1);
                ull bl = *(const ull*)(sBl + (nt * 8 + g) * 48 + ks * 16 + tg * 4);
                mma16816(acc[nt], h0, h1, h2, h3, (u32)bl, (u32)(bl >> 32));
            }
        }
    }

    int r0 = row0 + w * 16 + g;
#pragma unroll
    for (int nt = 0; nt < 16; nt++) {
        int col = nt * 8 + tg * 2;
        if (col < 64) {
            if (r0 < nrows)
                *(float2*)(C1 + (long)r0 * 64 + col) = make_float2(acc[nt][0], acc[nt][1]);
            if (r0 + 8 < nrows)
                *(float2*)(C1 + (long)(r0 + 8) * 64 + col) = make_float2(acc[nt][2], acc[nt][3]);
        } else {
            int c2 = col - 64;
            float2 bb = *(const float2*)(bias + c2);
            if (r0 < nrows)
                *(float2*)(C2 + (long)r0 * 64 + c2) =
                    make_float2(acc[nt][0] + bb.x, acc[nt][1] + bb.y);
            if (r0 + 8 < nrows)
                *(float2*)(C2 + (long)(r0 + 8) * 64 + c2) =
                    make_float2(acc[nt][2] + bb.x, acc[nt][3] + bb.y);
        }
    }
}

// ---------------- slot assignment + bitmap --------------------------------------
__global__ void slot_kernel(const int* __restrict__ targets,
                            const int* __restrict__ regions) {
    int idx = blockIdx.x * blockDim.x + threadIdx.x;
    if (idx >= BGRAPH * (AREG + 1)) return;
    int b = idx / (AREG + 1);
    int j = idx % (AREG + 1);
    int node = (j == AREG) ? targets[b] : regions[b * AREG + j];
    atomicOr(&d_bitmap[b * BMWORDS + (node >> 5)], 1u << (node & 31));
    int* p = &d_slotmap[b * NNODES + node];
    if (atomicCAS(p, -1, -2) == -1) {
        int s = atomicAdd(&d_counter[b], 1);
        atomicExch(p, s);
    }
}

// ---------------- conv2 scatter with smem bitmap filter -------------------------
__global__ void scatter2_kernel(const int* __restrict__ ne) {
    __shared__ unsigned sbm[BMWORDS];
    const int b = blockIdx.y;
    for (int i = threadIdx.x; i < BMWORDS; i += 320)
        sbm[i] = d_bitmap[b * BMWORDS + i];
    __syncthreads();

    const int lane = threadIdx.x & 31;
    const long base = (long)b * 2 * E2N;
    int e0 = blockIdx.x * 1600 + threadIdx.x;
#pragma unroll
    for (int it = 0; it < 5; it++) {
        int e = e0 + it * 320;
        int dst = ne[base + E2N + e];
        bool hit = (sbm[dst >> 5] >> (dst & 31)) & 1u;
        int slot = -1, src = 0;
        if (hit) {
            slot = d_slotmap[b * NNODES + dst];
            src = ne[base + e];
        }
        unsigned mask = __ballot_sync(0xffffffffu, hit);
        while (mask) {
            int bit = __ffs(mask) - 1;
            mask &= mask - 1;
            int es = __shfl_sync(0xffffffffu, src, bit);
            int sl = __shfl_sync(0xffffffffu, slot, bit);
            float2 v = ((const float2*)(d_gl + es * 64))[lane];
            float* p = d_acc2 + (b * SLOTS + sl) * 64 + 2 * lane;
            asm volatile("red.global.add.v2.f32 [%0], {%1,%2};"
                         :: "l"(p), "f"(v.x), "f"(v.y) : "memory");
            if (lane == 0) atomicAdd(&d_deg2[b * SLOTS + sl], 1.0f);
        }
    }
}

// ---------------- u_b = Wo @ t_b , c_b = bo . t_b -------------------------------
__global__ void u_kernel(const int* __restrict__ targets,
                         const float* __restrict__ Wo,
                         const float* __restrict__ bo) {
    int idx = blockIdx.x * blockDim.x + threadIdx.x;
    if (idx >= BGRAPH * HDIM) return;
    int b = idx >> 7;
    int h = idx & 127;
    int node = targets[b];
    int s = d_slotmap[b * NNODES + node];
    int base = (b * SLOTS + s) * 64;
    float inv = 1.f / fmaxf(d_deg2[b * SLOTS + s], 1.f);
    float acc = 0.f, c = 0.f;
#pragma unroll
    for (int d = 0; d < 64; d++) {
        float td = fmaxf(d_acc2[base + d] * inv + d_gr[node * 64 + d], 0.f);
        acc += Wo[h * 64 + d] * td;
        c += bo[d] * td;
    }
    d_u[idx] = acc;
    if (h == 0) d_c[b] = c;
}

// ---------------- final readout -------------------------------------------------
__global__ void final_kernel(const int* __restrict__ regions,
                             const float* __restrict__ Wm,
                             const float* __restrict__ bm,
                             float* __restrict__ q) {
    __shared__ float sWm[64 * 128];
    __shared__ float sreg[8][8][64];
    for (int i = threadIdx.x; i < 64 * 128; i += blockDim.x)
        sWm[i] = Wm[i];
    __syncthreads();

    const int lane = threadIdx.x & 31;
    const int wl = threadIdx.x >> 5;
    const float2 bmp0 = ((const float2*)bm)[lane];
    const float2 bmp1 = ((const float2*)bm)[lane + 32];

    for (int tile = blockIdx.x * 8 + wl; tile < 4000; tile += gridDim.x * 8) {
        int b = tile / 250;
#pragma unroll
        for (int r = 0; r < 8; r++) {
            int p = tile * 8 + r;
            int node = regions[p];
            int s = d_slotmap[b * NNODES + node];
            int base = (b * SLOTS + s) * 64;
            float inv = 1.f / fmaxf(d_deg2[b * SLOTS + s], 1.f);
            float2 a = ((const float2*)(d_acc2 + base))[lane];
            float2 g = ((const float2*)(d_gr + node * 64))[lane];
            sreg[wl][r][2 * lane]     = fmaxf(a.x * inv + g.x, 0.f);
            sreg[wl][r][2 * lane + 1] = fmaxf(a.y * inv + g.y, 0.f);
        }
        __syncwarp();

        ull acc0[8], acc1[8];
#pragma unroll
        for (int r = 0; r < 8; r++) { acc0[r] = 0ull; acc1[r] = 0ull; }

#pragma unroll 8
        for (int d = 0; d < 64; d++) {
            ull w0 = ((const ull*)(sWm + d * 128))[lane];
            ull w1 = ((const ull*)(sWm + d * 128 + 64))[lane];
#pragma unroll
            for (int r = 0; r < 8; r++) {
                float rd = sreg[wl][r][d];
                ull rdp = pack2(rd, rd);
                acc0[r] = ffma2(rdp, w0, acc0[r]);
                acc1[r] = ffma2(rdp, w1, acc1[r]);
            }
        }

        const float2* ubp = (const float2*)(d_u + b * HDIM);
        float2 u0 = ubp[lane];
        float2 u1 = ubp[lane + 32];
        float cb = d_c[b];
#pragma unroll
        for (int r = 0; r < 8; r++) {
            float m0, m1, m2, m3;
            unpack2(acc0[r], m0, m1);
            unpack2(acc1[r], m2, m3);
            float sum = fmaxf(m0 + bmp0.x, 0.f) * u0.x
                      + fmaxf(m1 + bmp0.y, 0.f) * u0.y
                      + fmaxf(m2 + bmp1.x, 0.f) * u1.x
                      + fmaxf(m3 + bmp1.y, 0.f) * u1.y;
#pragma unroll
            for (int o = 16; o > 0; o >>= 1)
                sum += __shfl_down_sync(0xffffffffu, sum, o);
            if (lane == 0) q[tile * 8 + r] = sum + cb;
        }
        __syncwarp();
    }
}

// ---------------- launch ---------------------------------------------------------
extern "C" void kernel_launch(void* const* d_in, const int* in_sizes, int n_in,
                              void* d_out, int out_size) {
    const float* x       = (const float*)d_in[0];
    const int*   ei      = (const int*)  d_in[1];
    const int*   ne      = (const int*)  d_in[2];
    const int*   targets = (const int*)  d_in[3];
    const int*   regions = (const int*)  d_in[4];
    const float* W1l     = (const float*)d_in[5];
    const float* W1r     = (const float*)d_in[6];
    const float* b1      = (const float*)d_in[7];
    const float* W2l     = (const float*)d_in[8];
    const float* W2r     = (const float*)d_in[9];
    const float* b2      = (const float*)d_in[10];
    const float* Wm      = (const float*)d_in[11];
    const float* bm      = (const float*)d_in[12];
    const float* Wo      = (const float*)d_in[13];
    const float* bo      = (const float*)d_in[14];
    float* q = (float*)d_out;

    float *p_yl, *p_yr, *p_gl, *p_gr;
    u32 *p_B1h, *p_B1l, *p_B2h, *p_B2l;
    cudaGetSymbolAddress((void**)&p_yl, d_yl);
    cudaGetSymbolAddress((void**)&p_yr, d_yr);
    cudaGetSymbolAddress((void**)&p_gl, d_gl);
    cudaGetSymbolAddress((void**)&p_gr, d_gr);
    cudaGetSymbolAddress((void**)&p_B1h, d_B1h);
    cudaGetSymbolAddress((void**)&p_B1l, d_B1l);
    cudaGetSymbolAddress((void**)&p_B2h, d_B2h);
    cudaGetSymbolAddress((void**)&p_B2l, d_B2l);

    cudaFuncSetAttribute(mma_gemm1, cudaFuncAttributeMaxDynamicSharedMemorySize, 86016);
    cudaFuncSetAttribute(mma_gemm2, cudaFuncAttributeMaxDynamicSharedMemorySize, 83968);

    // 0. weight preconversion + cnt clear
    {
        int threads = 768 + NNODES / 4;
        prep_w_kernel<<<(threads + 255) / 256, 256>>>(W1l, W1r, W2l, W2r);
    }

    // 1. GEMM1: yl = x@W1l ; yr = x@W1r + b1
    mma_gemm1<<<391, 256, 86016>>>(x, p_B1h, p_B1l, b1, p_yl, p_yr, NNODES);

    // 2. conv1 bucket fill
    fill_kernel<<<(E1N / 4 + 255) / 256, 256>>>(ei);

    // 3. conv1 gather -> h1    <-- profiled slot
    gather1_kernel<<<(NNODES / 2 * 32) / 256, 256>>>();

    // 4. clear scratch (acc2/slotmap/bitmap/deg2/counter)
    clear_kernel<<<(CLR_TOTAL + 255) / 256, 256>>>();

    // 5. GEMM2: gl = h1@W2l ; gr = h1@W2r + b2
    mma_gemm2<<<391, 256, 83968>>>(p_B2h, p_B2l, b2, p_gl, p_gr, NNODES);

    // 6. slot assignment + bitmap
    slot_kernel<<<(BGRAPH * (AREG + 1) + 255) / 256, 256>>>(targets, regions);

    // 7. conv2 scatter with smem bitmap filter
    {
        dim3 grid(125, BGRAPH);
        scatter2_kernel<<<grid, 320>>>(ne);
    }

    // 8. u_b = Wo @ t_b, c_b
    u_kernel<<<(BGRAPH * HDIM + 255) / 256, 256>>>(targets, Wo, bo);

    // 9. readout
    final_kernel<<<250, 256>>>(regions, Wm, bm, q);
}

// round 14
// speedup vs baseline: 1.4078x; 1.1197x over previous
#include <cuda_runtime.h>
#include <cuda_bf16.h>

#define NNODES 50000
#define FIN    128
#define DDIM   64
#define HDIM   128
#define BGRAPH 16
#define E1N    800000
#define E2N    200000
#define AREG   2000
#define NREG   (BGRAPH * AREG)   // 32000
#define SLOTS  2048
#define BMWORDS 1568
#define DEGCAP 96

typedef unsigned long long ull;
typedef unsigned int u32;

// ---------------- helpers -------------------------------------------------------
__device__ __forceinline__ u32 bf2_hi(float a, float b) {
    __nv_bfloat162 h = __floats2bfloat162_rn(a, b);
    return *reinterpret_cast<u32*>(&h);
}
__device__ __forceinline__ u32 bf2_lo(float a, float b) {
    float ra = a - __bfloat162float(__float2bfloat16(a));
    float rb = b - __bfloat162float(__float2bfloat16(b));
    __nv_bfloat162 l = __floats2bfloat162_rn(ra, rb);
    return *reinterpret_cast<u32*>(&l);
}
__device__ __forceinline__ void mma16816(float* c, u32 a0, u32 a1, u32 a2, u32 a3,
                                         u32 b0, u32 b1) {
    asm("mma.sync.aligned.m16n8k16.row.col.f32.bf16.bf16.f32 "
        "{%0,%1,%2,%3}, {%4,%5,%6,%7}, {%8,%9}, {%0,%1,%2,%3};"
        : "+f"(c[0]), "+f"(c[1]), "+f"(c[2]), "+f"(c[3])
        : "r"(a0), "r"(a1), "r"(a2), "r"(a3), "r"(b0), "r"(b1));
}
__device__ __forceinline__ u32 smem_u32(const void* p) {
    u32 a;
    asm("{ .reg .u64 t; cvta.to.shared.u64 t, %1; cvt.u32.u64 %0, t; }"
        : "=r"(a) : "l"(p));
    return a;
}
__device__ __forceinline__ void cpa16(u32 smem_addr, const void* gptr) {
    asm volatile("cp.async.cg.shared.global [%0], [%1], 16;"
                 :: "r"(smem_addr), "l"(gptr) : "memory");
}
__device__ __forceinline__ void cpa16z(u32 smem_addr, const void* gptr, u32 sz) {
    asm volatile("cp.async.cg.shared.global [%0], [%1], 16, %2;"
                 :: "r"(smem_addr), "l"(gptr), "r"(sz) : "memory");
}
#define CP_COMMIT() asm volatile("cp.async.commit_group;" ::: "memory")
#define CP_WAIT0()  asm volatile("cp.async.wait_group 0;" ::: "memory")

__host__ __device__ __forceinline__ int pp_of(int jg) {
    return ((jg >> 2) & 1) + (jg & 3) * 2 + (jg >> 3) * 8;
}

// ---------------- scratch -------------------------------------------------------
__device__ __align__(16) float d_yl[NNODES * DDIM];
__device__ __align__(16) float d_yr[NNODES * DDIM];
__device__ __align__(16) float d_h1[NNODES * DDIM];
__device__ __align__(16) int   d_cnt[NNODES];
__device__ __align__(16) int   d_csr[NNODES * DEGCAP];
__device__ __align__(16) float d_gl[NNODES * DDIM];
__device__ __align__(16) float d_gr[NNODES * DDIM];
__device__ __align__(16) int   d_slotmap[BGRAPH * NNODES];
__device__ __align__(16) unsigned d_bitmap[BGRAPH * BMWORDS];
__device__ __align__(16) int   d_counter[BGRAPH];
__device__ __align__(16) float d_acc2[BGRAPH * SLOTS * DDIM];
__device__ __align__(16) float d_deg2[BGRAPH * SLOTS];
__device__ __align__(16) float d_u[BGRAPH * HDIM];
__device__ __align__(16) float d_c[BGRAPH];
__device__ __align__(16) float d_h2r[NREG * DDIM];     // region h2 rows, flat
// preconverted weights (pair-permuted bf16 split; chunk-major [c][n][24])
__device__ __align__(16) u32 d_B1h[4 * 128 * 24];
__device__ __align__(16) u32 d_B1l[4 * 128 * 24];
__device__ __align__(16) u32 d_B2h[2 * 128 * 24];
__device__ __align__(16) u32 d_B2l[2 * 128 * 24];
__device__ __align__(16) u32 d_Wmh[2 * 128 * 24];
__device__ __align__(16) u32 d_Wml[2 * 128 * 24];

// ---------------- clear kernel (acc2/slotmap/bitmap/deg2/counter) ---------------
static constexpr int CLR_ACC2 = BGRAPH * SLOTS * DDIM / 4;
static constexpr int CLR_SMAP = BGRAPH * NNODES / 4;
static constexpr int CLR_BMAP = BGRAPH * BMWORDS / 4;
static constexpr int CLR_DEG2 = BGRAPH * SLOTS / 4;
static constexpr int CLR_CNT  = BGRAPH / 4;
static constexpr int CLR_TOTAL = CLR_ACC2 + CLR_SMAP + CLR_BMAP + CLR_DEG2 + CLR_CNT;

__global__ void clear_kernel() {
    int i = blockIdx.x * blockDim.x + threadIdx.x;
    float4 z = make_float4(0.f, 0.f, 0.f, 0.f);
    if (i < CLR_ACC2) { ((float4*)d_acc2)[i] = z; return; }
    i -= CLR_ACC2;
    if (i < CLR_SMAP) { ((int4*)d_slotmap)[i] = make_int4(-1, -1, -1, -1); return; }
    i -= CLR_SMAP;
    if (i < CLR_BMAP) { ((uint4*)d_bitmap)[i] = make_uint4(0, 0, 0, 0); return; }
    i -= CLR_BMAP;
    if (i < CLR_DEG2) { ((float4*)d_deg2)[i] = z; return; }
    i -= CLR_DEG2;
    if (i < CLR_CNT)  { ((int4*)d_counter)[i] = make_int4(0, 0, 0, 0); }
}

// ---------------- weight preconversion (B1, B2, Wm) + cnt clear -----------------
__global__ void prep_w_kernel(const float* __restrict__ W1l,
                              const float* __restrict__ W1r,
                              const float* __restrict__ W2l,
                              const float* __restrict__ W2r,
                              const float* __restrict__ Wm) {
    int tid = blockIdx.x * blockDim.x + threadIdx.x;
    if (tid < 512) {
        int c = tid >> 7, n = tid & 127;
        const float* W = (n < 64) ? W1l : W1r;
        int nc = n & 63;
        u32* oh = d_B1h + (c * 128 + n) * 24;
        u32* ol = d_B1l + (c * 128 + n) * 24;
#pragma unroll
        for (int jg = 0; jg < 16; jg++) {
            int k = c * 32 + 2 * jg;
            float wx = W[k * 64 + nc];
            float wy = W[(k + 1) * 64 + nc];
            int pp = pp_of(jg);
            oh[pp] = bf2_hi(wx, wy);
            ol[pp] = bf2_lo(wx, wy);
        }
    } else if (tid < 768) {
        int id = tid - 512;
        int c = id >> 7, n = id & 127;
        const float* W = (n < 64) ? W2l : W2r;
        int nc = n & 63;
        u32* oh = d_B2h + (c * 128 + n) * 24;
        u32* ol = d_B2l + (c * 128 + n) * 24;
#pragma unroll
        for (int jg = 0; jg < 16; jg++) {
            int k = c * 32 + 2 * jg;
            float wx = W[k * 64 + nc];
            float wy = W[(k + 1) * 64 + nc];
            int pp = pp_of(jg);
            oh[pp] = bf2_hi(wx, wy);
            ol[pp] = bf2_lo(wx, wy);
        }
    } else if (tid < 1024) {
        int id = tid - 768;                   // Wm: 2 chunks x 128 n
        int c = id >> 7, n = id & 127;
        u32* oh = d_Wmh + (c * 128 + n) * 24;
        u32* ol = d_Wml + (c * 128 + n) * 24;
#pragma unroll
        for (int jg = 0; jg < 16; jg++) {
            int k = c * 32 + 2 * jg;
            float wx = Wm[k * 128 + n];
            float wy = Wm[(k + 1) * 128 + n];
            int pp = pp_of(jg);
            oh[pp] = bf2_hi(wx, wy);
            ol[pp] = bf2_lo(wx, wy);
        }
    } else {
        int id = tid - 1024;                  // clear d_cnt
        if (id < NNODES / 4)
            ((int4*)d_cnt)[id] = make_int4(0, 0, 0, 0);
    }
}

// ---------------- conv1 bucket fill ---------------------------------------------
__global__ void fill_kernel(const int* __restrict__ ei) {
    int idx = (blockIdx.x * blockDim.x + threadIdx.x) * 4;
    if (idx >= E1N) return;
    int4 s = *(const int4*)(ei + idx);
    int4 d = *(const int4*)(ei + E1N + idx);
    int o0 = atomicAdd(&d_cnt[d.x], 1);
    int o1 = atomicAdd(&d_cnt[d.y], 1);
    int o2 = atomicAdd(&d_cnt[d.z], 1);
    int o3 = atomicAdd(&d_cnt[d.w], 1);
    d_csr[d.x * DEGCAP + o0] = s.x;
    d_csr[d.y * DEGCAP + o1] = s.y;
    d_csr[d.z * DEGCAP + o2] = s.z;
    d_csr[d.w * DEGCAP + o3] = s.w;
}

// ---------------- conv1 gather: index-batched (16 idx upfront via 4x LDG.128) ---
__global__ void gather1_kernel() {
    int tid = blockIdx.x * blockDim.x + threadIdx.x;
    int w = tid >> 5, lane = tid & 31;
    int node = 2 * w + (lane >> 4);
    int j = lane & 15;
    int deg = d_cnt[node];
    const int4* csr4 = (const int4*)(d_csr + node * DEGCAP);
    float4 acc = make_float4(0.f, 0.f, 0.f, 0.f);
    for (int i0 = 0; i0 < deg; i0 += 16) {
        int q = i0 >> 2;
        int4 a = csr4[q], b = csr4[q + 1], c = csr4[q + 2], d4 = csr4[q + 3];
        int idx[16] = {a.x, a.y, a.z, a.w, b.x, b.y, b.z, b.w,
                       c.x, c.y, c.z, c.w, d4.x, d4.y, d4.z, d4.w};
#pragma unroll
        for (int u = 0; u < 16; u++) {
            if (i0 + u < deg) {
                float4 v = ((const float4*)(d_yl + idx[u] * 64))[j];
                acc.x += v.x; acc.y += v.y; acc.z += v.z; acc.w += v.w;
            }
        }
    }
    float inv = 1.f / fmaxf((float)deg, 1.f);
    float4 y = ((const float4*)(d_yr + node * 64))[j];
    float4 h;
    h.x = fmaxf(acc.x * inv + y.x, 0.f);
    h.y = fmaxf(acc.y * inv + y.y, 0.f);
    h.z = fmaxf(acc.z * inv + y.z, 0.f);
    h.w = fmaxf(acc.w * inv + y.w, 0.f);
    ((float4*)(d_h1 + node * 64))[j] = h;
}

// ================= GEMM1: D[128,128] = x @ [W1l|W1r], cp.async 2-buffer =========
__global__ __launch_bounds__(256) void mma_gemm1(const float* __restrict__ X,
                                                 const u32* __restrict__ Bgh,
                                                 const u32* __restrict__ Bgl,
                                                 const float* __restrict__ bias,
                                                 float* __restrict__ C1,
                                                 float* __restrict__ C2,
                                                 int nrows) {
    extern __shared__ u32 sm[];
    const int t = threadIdx.x;
    const int w = t >> 5, lane = t & 31;
    const int g = lane >> 2, tg = lane & 3;
    const int row0 = blockIdx.x * 128;

    float acc[16][4];
#pragma unroll
    for (int nt = 0; nt < 16; nt++)
#pragma unroll
        for (int i = 0; i < 4; i++) acc[nt][i] = 0.f;

    auto copy_chunk = [&](int c, int buf) {
        u32 sbase = smem_u32(sm + buf * 10752);
#pragma unroll
        for (int i = 0; i < 4; i++) {
            int idx = t + i * 256;
            int row = idx >> 3, gc = idx & 7;
            int grow = row0 + row;
            u32 sz = (grow < nrows) ? 16u : 0u;
            const float* src = X + (long)min(grow, nrows - 1) * 128 + c * 32 + gc * 4;
            cpa16z(sbase + (row * 36 + gc * 4) * 4, src, sz);
        }
#pragma unroll
        for (int i = 0; i < 3; i++) {
            int idx = t + i * 256;
            cpa16(sbase + 4608 * 4 + idx * 16, Bgh + c * 3072 + idx * 4);
            cpa16(sbase + 7680 * 4 + idx * 16, Bgl + c * 3072 + idx * 4);
        }
        CP_COMMIT();
    };

    copy_chunk(0, 0);

#pragma unroll
    for (int c = 0; c < 4; c++) {
        CP_WAIT0();
        __syncthreads();
        if (c + 1 < 4) copy_chunk(c + 1, (c + 1) & 1);

        const float* sAf = (const float*)(sm + (c & 1) * 10752);
        const __nv_bfloat16* sBh = (const __nv_bfloat16*)(sm + (c & 1) * 10752 + 4608);
        const __nv_bfloat16* sBl = (const __nv_bfloat16*)(sm + (c & 1) * 10752 + 7680);

#pragma unroll
        for (int ks = 0; ks < 2; ks++) {
            const float* Ar0 = sAf + (w * 16 + g) * 36 + ks * 16 + 2 * tg;
            const float* Ar1 = Ar0 + 8 * 36;
            float2 p00 = *(const float2*)Ar0;
            float2 p02 = *(const float2*)(Ar0 + 8);
            float2 p10 = *(const float2*)Ar1;
            float2 p12 = *(const float2*)(Ar1 + 8);
            u32 h0 = bf2_hi(p00.x, p00.y), h2 = bf2_hi(p02.x, p02.y);
            u32 h1 = bf2_hi(p10.x, p10.y), h3 = bf2_hi(p12.x, p12.y);
            u32 l0 = bf2_lo(p00.x, p00.y), l2 = bf2_lo(p02.x, p02.y);
            u32 l1 = bf2_lo(p10.x, p10.y), l3 = bf2_lo(p12.x, p12.y);
#pragma unroll
            for (int nt = 0; nt < 16; nt++) {
                ull bh = *(const ull*)(sBh + (nt * 8 + g) * 48 + ks * 16 + tg * 4);
                u32 bh0 = (u32)bh, bh1 = (u32)(bh >> 32);
                mma16816(acc[nt], h0, h1, h2, h3, bh0, bh1);
                mma16816(acc[nt], l0, l1, l2, l3, bh0, bh1);
                ull bl = *(const ull*)(sBl + (nt * 8 + g) * 48 + ks * 16 + tg * 4);
                mma16816(acc[nt], h0, h1, h2, h3, (u32)bl, (u32)(bl >> 32));
            }
        }
        __syncthreads();
    }

    int r0 = row0 + w * 16 + g;
#pragma unroll
    for (int nt = 0; nt < 16; nt++) {
        int col = nt * 8 + tg * 2;
        if (col < 64) {
            if (r0 < nrows)
                *(float2*)(C1 + (long)r0 * 64 + col) = make_float2(acc[nt][0], acc[nt][1]);
            if (r0 + 8 < nrows)
                *(float2*)(C1 + (long)(r0 + 8) * 64 + col) = make_float2(acc[nt][2], acc[nt][3]);
        } else {
            int c2 = col - 64;
            float2 bb = *(const float2*)(bias + c2);
            if (r0 < nrows)
                *(float2*)(C2 + (long)r0 * 64 + c2) =
                    make_float2(acc[nt][0] + bb.x, acc[nt][1] + bb.y);
            if (r0 + 8 < nrows)
                *(float2*)(C2 + (long)(r0 + 8) * 64 + c2) =
                    make_float2(acc[nt][2] + bb.x, acc[nt][3] + bb.y);
        }
    }
}

// ================= GEMM2: D = h1 @ [W2l|W2r], single upfront load ===============
__global__ __launch_bounds__(256) void mma_gemm2(const u32* __restrict__ Bgh,
                                                 const u32* __restrict__ Bgl,
                                                 const float* __restrict__ bias,
                                                 float* __restrict__ C1,
                                                 float* __restrict__ C2,
                                                 int nrows) {
    extern __shared__ u32 sm[];
    const int t = threadIdx.x;
    const int w = t >> 5, lane = t & 31;
    const int g = lane >> 2, tg = lane & 3;
    const int row0 = blockIdx.x * 128;

    {
        u32 sh = smem_u32(sm);
#pragma unroll
        for (int i = 0; i < 8; i++) {
            int idx = t + i * 256;
            int row = idx >> 4, gc = idx & 15;
            int grow = row0 + row;
            u32 sz = (grow < nrows) ? 16u : 0u;
            cpa16z(sh + (row * 68 + gc * 4) * 4,
                   d_h1 + (long)min(grow, nrows - 1) * 64 + gc * 4, sz);
        }
        u32 sb = smem_u32(sm + 8704);
#pragma unroll
        for (int i = 0; i < 6; i++) {
            int idx = t + i * 256;
            cpa16(sb + idx * 16, Bgh + idx * 4);
            cpa16(sb + 6144 * 4 + idx * 16, Bgl + idx * 4);
        }
        CP_COMMIT();
        CP_WAIT0();
        __syncthreads();
    }

    float acc[16][4];
#pragma unroll
    for (int nt = 0; nt < 16; nt++)
#pragma unroll
        for (int i = 0; i < 4; i++) acc[nt][i] = 0.f;

    const float* sH = (const float*)sm;

#pragma unroll
    for (int c = 0; c < 2; c++) {
        const __nv_bfloat16* sBh = (const __nv_bfloat16*)(sm + 8704 + c * 3072);
        const __nv_bfloat16* sBl = (const __nv_bfloat16*)(sm + 14848 + c * 3072);
#pragma unroll
        for (int ks = 0; ks < 2; ks++) {
            const float* Ar0 = sH + (w * 16 + g) * 68 + c * 32 + ks * 16 + 2 * tg;
            const float* Ar1 = Ar0 + 8 * 68;
            float2 p00 = *(const float2*)Ar0;
            float2 p02 = *(const float2*)(Ar0 + 8);
            float2 p10 = *(const float2*)Ar1;
            float2 p12 = *(const float2*)(Ar1 + 8);
            u32 h0 = bf2_hi(p00.x, p00.y), h2 = bf2_hi(p02.x, p02.y);
            u32 h1 = bf2_hi(p10.x, p10.y), h3 = bf2_hi(p12.x, p12.y);
            u32 l0 = bf2_lo(p00.x, p00.y), l2 = bf2_lo(p02.x, p02.y);
            u32 l1 = bf2_lo(p10.x, p10.y), l3 = bf2_lo(p12.x, p12.y);
#pragma unroll
            for (int nt = 0; nt < 16; nt++) {
                ull bh = *(const ull*)(sBh + (nt * 8 + g) * 48 + ks * 16 + tg * 4);
                u32 bh0 = (u32)bh, bh1 = (u32)(bh >> 32);
                mma16816(acc[nt], h0, h1, h2, h3, bh0, bh1);
                mma16816(acc[nt], l0, l1, l2, l3, bh0, bh1);
                ull bl = *(const ull*)(sBl + (nt * 8 + g) * 48 + ks * 16 + tg * 4);
                mma16816(acc[nt], h0, h1, h2, h3, (u32)bl, (u32)(bl >> 32));
            }
        }
    }

    int r0 = row0 + w * 16 + g;
#pragma unroll
    for (int nt = 0; nt < 16; nt++) {
        int col = nt * 8 + tg * 2;
        if (col < 64) {
            if (r0 < nrows)
                *(float2*)(C1 + (long)r0 * 64 + col) = make_float2(acc[nt][0], acc[nt][1]);
            if (r0 + 8 < nrows)
                *(float2*)(C1 + (long)(r0 + 8) * 64 + col) = make_float2(acc[nt][2], acc[nt][3]);
        } else {
            int c2 = col - 64;
            float2 bb = *(const float2*)(bias + c2);
            if (r0 < nrows)
                *(float2*)(C2 + (long)r0 * 64 + c2) =
                    make_float2(acc[nt][0] + bb.x, acc[nt][1] + bb.y);
            if (r0 + 8 < nrows)
                *(float2*)(C2 + (long)(r0 + 8) * 64 + c2) =
                    make_float2(acc[nt][2] + bb.x, acc[nt][3] + bb.y);
        }
    }
}

// ---------------- slot assignment + bitmap --------------------------------------
__global__ void slot_kernel(const int* __restrict__ targets,
                            const int* __restrict__ regions) {
    int idx = blockIdx.x * blockDim.x + threadIdx.x;
    if (idx >= BGRAPH * (AREG + 1)) return;
    int b = idx / (AREG + 1);
    int j = idx % (AREG + 1);
    int node = (j == AREG) ? targets[b] : regions[b * AREG + j];
    atomicOr(&d_bitmap[b * BMWORDS + (node >> 5)], 1u << (node & 31));
    int* p = &d_slotmap[b * NNODES + node];
    if (atomicCAS(p, -1, -2) == -1) {
        int s = atomicAdd(&d_counter[b], 1);
        atomicExch(p, s);
    }
}

// ---------------- conv2 scatter with smem bitmap filter -------------------------
__global__ void scatter2_kernel(const int* __restrict__ ne) {
    __shared__ unsigned sbm[BMWORDS];
    const int b = blockIdx.y;
    for (int i = threadIdx.x; i < BMWORDS; i += 320)
        sbm[i] = d_bitmap[b * BMWORDS + i];
    __syncthreads();

    const int lane = threadIdx.x & 31;
    const long base = (long)b * 2 * E2N;
    int e0 = blockIdx.x * 1600 + threadIdx.x;
#pragma unroll
    for (int it = 0; it < 5; it++) {
        int e = e0 + it * 320;
        int dst = ne[base + E2N + e];
        bool hit = (sbm[dst >> 5] >> (dst & 31)) & 1u;
        int slot = -1, src = 0;
        if (hit) {
            slot = d_slotmap[b * NNODES + dst];
            src = ne[base + e];
        }
        unsigned mask = __ballot_sync(0xffffffffu, hit);
        while (mask) {
            int bit = __ffs(mask) - 1;
            mask &= mask - 1;
            int es = __shfl_sync(0xffffffffu, src, bit);
            int sl = __shfl_sync(0xffffffffu, slot, bit);
            float2 v = ((const float2*)(d_gl + es * 64))[lane];
            float* p = d_acc2 + (b * SLOTS + sl) * 64 + 2 * lane;
            asm volatile("red.global.add.v2.f32 [%0], {%1,%2};"
                         :: "l"(p), "f"(v.x), "f"(v.y) : "memory");
            if (lane == 0) atomicAdd(&d_deg2[b * SLOTS + sl], 1.0f);
        }
    }
}

// ---------------- u_b = Wo @ t_b , c_b = bo . t_b -------------------------------
__global__ void u_kernel(const int* __restrict__ targets,
                         const float* __restrict__ Wo,
                         const float* __restrict__ bo) {
    int idx = blockIdx.x * blockDim.x + threadIdx.x;
    if (idx >= BGRAPH * HDIM) return;
    int b = idx >> 7;
    int h = idx & 127;
    int node = targets[b];
    int s = d_slotmap[b * NNODES + node];
    int base = (b * SLOTS + s) * 64;
    float inv = 1.f / fmaxf(d_deg2[b * SLOTS + s], 1.f);
    float acc = 0.f, c = 0.f;
#pragma unroll
    for (int d = 0; d < 64; d++) {
        float td = fmaxf(d_acc2[base + d] * inv + d_gr[node * 64 + d], 0.f);
        acc += Wo[h * 64 + d] * td;
        c += bo[d] * td;
    }
    d_u[idx] = acc;
    if (h == 0) d_c[b] = c;
}

// ---------------- h2r materialization: h2r[p] = relu(acc2/deg2 + gr) ------------
__global__ void h2r_kernel(const int* __restrict__ regions) {
    int tid = blockIdx.x * blockDim.x + threadIdx.x;
    int w = tid >> 5, lane = tid & 31;
    int p = 2 * w + (lane >> 4);
    if (p >= NREG) return;
    int j = lane & 15;
    int b = p / AREG;
    int node = regions[p];
    int s = d_slotmap[b * NNODES + node];
    int base = (b * SLOTS + s) * 64;
    float inv = 1.f / fmaxf(d_deg2[b * SLOTS + s], 1.f);
    float4 a = ((const float4*)(d_acc2 + base))[j];
    float4 g = ((const float4*)(d_gr + node * 64))[j];
    float4 h;
    h.x = fmaxf(a.x * inv + g.x, 0.f);
    h.y = fmaxf(a.y * inv + g.y, 0.f);
    h.z = fmaxf(a.z * inv + g.z, 0.f);
    h.w = fmaxf(a.w * inv + g.w, 0.f);
    ((float4*)(d_h2r + p * 64))[j] = h;
}

// ================= final readout as HMMA GEMM ===================================
// Per CTA: rows = 128 region positions, E = relu(h2r @ Wm + bm) [128, 128],
// q[p] = E[p,:] . u[b(p),:] + c[b(p)].
// smem (u32): sH 8704 | sBh 6144 | sBl 6144 | su 2048 | sbm 128 | sc 16 = 23184
__global__ __launch_bounds__(256) void final_mma(const float* __restrict__ bm,
                                                 float* __restrict__ q) {
    extern __shared__ u32 sm[];
    const int t = threadIdx.x;
    const int w = t >> 5, lane = t & 31;
    const int g = lane >> 2, tg = lane & 3;
    const int row0 = blockIdx.x * 128;

    {
        u32 sh = smem_u32(sm);
#pragma unroll
        for (int i = 0; i < 8; i++) {          // h2r rows: 2048 granules
            int idx = t + i * 256;
            int row = idx >> 4, gc = idx & 15;
            cpa16(sh + (row * 68 + gc * 4) * 4,
                  d_h2r + (long)(row0 + row) * 64 + gc * 4);
        }
        u32 sb = smem_u32(sm + 8704);
#pragma unroll
        for (int i = 0; i < 6; i++) {
            int idx = t + i * 256;
            cpa16(sb + idx * 16, d_Wmh + idx * 4);
            cpa16(sb + 6144 * 4 + idx * 16, d_Wml + idx * 4);
        }
        u32 su = smem_u32(sm + 20992);
#pragma unroll
        for (int i = 0; i < 2; i++) {          // u: 512 granules
            int idx = t + i * 256;
            cpa16(su + idx * 16, d_u + idx * 4);
        }
        if (t < 32) cpa16(smem_u32(sm + 23040) + t * 16, bm + t * 4);
        if (t < 4)  cpa16(smem_u32(sm + 23168) + t * 16, d_c + t * 4);
        CP_COMMIT();
        CP_WAIT0();
        __syncthreads();
    }

    float acc[16][4];
#pragma unroll
    for (int nt = 0; nt < 16; nt++)
#pragma unroll
        for (int i = 0; i < 4; i++) acc[nt][i] = 0.f;

    const float* sH = (const float*)sm;

#pragma unroll
    for (int c = 0; c < 2; c++) {
        const __nv_bfloat16* sBh = (const __nv_bfloat16*)(sm + 8704 + c * 3072);
        const __nv_bfloat16* sBl = (const __nv_bfloat16*)(sm + 14848 + c * 3072);
#pragma unroll
        for (int ks = 0; ks < 2; ks++) {
            const float* Ar0 = sH + (w * 16 + g) * 68 + c * 32 + ks * 16 + 2 * tg;
            const float* Ar1 = Ar0 + 8 * 68;
            float2 p00 = *(const float2*)Ar0;
            float2 p02 = *(const float2*)(Ar0 + 8);
            float2 p10 = *(const float2*)Ar1;
            float2 p12 = *(const float2*)(Ar1 + 8);
            u32 h0 = bf2_hi(p00.x, p00.y), h2 = bf2_hi(p02.x, p02.y);
            u32 h1 = bf2_hi(p10.x, p10.y), h3 = bf2_hi(p12.x, p12.y);
            u32 l0 = bf2_lo(p00.x, p00.y), l2 = bf2_lo(p02.x, p02.y);
            u32 l1 = bf2_lo(p10.x, p10.y), l3 = bf2_lo(p12.x, p12.y);
#pragma unroll
            for (int nt = 0; nt < 16; nt++) {
                ull bh = *(const ull*)(sBh + (nt * 8 + g) * 48 + ks * 16 + tg * 4);
                u32 bh0 = (u32)bh, bh1 = (u32)(bh >> 32);
                mma16816(acc[nt], h0, h1, h2, h3, bh0, bh1);
                mma16816(acc[nt], l0, l1, l2, l3, bh0, bh1);
                ull bl = *(const ull*)(sBl + (nt * 8 + g) * 48 + ks * 16 + tg * 4);
                mma16816(acc[nt], h0, h1, h2, h3, (u32)bl, (u32)(bl >> 32));
            }
        }
    }

    // ---- epilogue: relu(+bm) . u[b], quad reduce, + c[b] ----
    const float* su = (const float*)(sm + 20992);
    const float* sbm = (const float*)(sm + 23040);
    const float* sc = (const float*)(sm + 23168);
    int p0 = row0 + w * 16 + g;
    int p1 = p0 + 8;
    int b0 = p0 / AREG, b1 = p1 / AREG;
    const float* u0 = su + b0 * 128;
    const float* u1 = su + b1 * 128;
    float s0 = 0.f, s1 = 0.f;
#pragma unroll
    for (int nt = 0; nt < 16; nt++) {
        int col = nt * 8 + tg * 2;
        float bx = sbm[col], by = sbm[col + 1];
        s0 += fmaxf(acc[nt][0] + bx, 0.f) * u0[col]
            + fmaxf(acc[nt][1] + by, 0.f) * u0[col + 1];
        s1 += fmaxf(acc[nt][2] + bx, 0.f) * u1[col]
            + fmaxf(acc[nt][3] + by, 0.f) * u1[col + 1];
    }
    s0 += __shfl_xor_sync(0xffffffffu, s0, 1);
    s0 += __shfl_xor_sync(0xffffffffu, s0, 2);
    s1 += __shfl_xor_sync(0xffffffffu, s1, 1);
    s1 += __shfl_xor_sync(0xffffffffu, s1, 2);
    if (tg == 0) {
        q[p0] = s0 + sc[b0];
        q[p1] = s1 + sc[b1];
    }
}

// ---------------- launch ---------------------------------------------------------
extern "C" void kernel_launch(void* const* d_in, const int* in_sizes, int n_in,
                              void* d_out, int out_size) {
    const float* x       = (const float*)d_in[0];
    const int*   ei      = (const int*)  d_in[1];
    const int*   ne      = (const int*)  d_in[2];
    const int*   targets = (const int*)  d_in[3];
    const int*   regions = (const int*)  d_in[4];
    const float* W1l     = (const float*)d_in[5];
    const float* W1r     = (const float*)d_in[6];
    const float* b1      = (const float*)d_in[7];
    const float* W2l     = (const float*)d_in[8];
    const float* W2r     = (const float*)d_in[9];
    const float* b2      = (const float*)d_in[10];
    const float* Wm      = (const float*)d_in[11];
    const float* bm      = (const float*)d_in[12];
    const float* Wo      = (const float*)d_in[13];
    const float* bo      = (const float*)d_in[14];
    float* q = (float*)d_out;

    float *p_yl, *p_yr, *p_gl, *p_gr;
    u32 *p_B1h, *p_B1l, *p_B2h, *p_B2l;
    cudaGetSymbolAddress((void**)&p_yl, d_yl);
    cudaGetSymbolAddress((void**)&p_yr, d_yr);
    cudaGetSymbolAddress((void**)&p_gl, d_gl);
    cudaGetSymbolAddress((void**)&p_gr, d_gr);
    cudaGetSymbolAddress((void**)&p_B1h, d_B1h);
    cudaGetSymbolAddress((void**)&p_B1l, d_B1l);
    cudaGetSymbolAddress((void**)&p_B2h, d_B2h);
    cudaGetSymbolAddress((void**)&p_B2l, d_B2l);

    cudaFuncSetAttribute(mma_gemm1, cudaFuncAttributeMaxDynamicSharedMemorySize, 86016);
    cudaFuncSetAttribute(mma_gemm2, cudaFuncAttributeMaxDynamicSharedMemorySize, 83968);
    cudaFuncSetAttribute(final_mma, cudaFuncAttributeMaxDynamicSharedMemorySize, 92736);

    // 0. weight preconversion (B1, B2, Wm) + cnt clear
    {
        int threads = 1024 + NNODES / 4;
        prep_w_kernel<<<(threads + 255) / 256, 256>>>(W1l, W1r, W2l, W2r, Wm);
    }

    // 1. GEMM1: yl = x@W1l ; yr = x@W1r + b1
    mma_gemm1<<<391, 256, 86016>>>(x, p_B1h, p_B1l, b1, p_yl, p_yr, NNODES);

    // 2. conv1 bucket fill
    fill_kernel<<<(E1N / 4 + 255) / 256, 256>>>(ei);

    // 3. conv1 gather -> h1    <-- profiled slot
    gather1_kernel<<<(NNODES / 2 * 32) / 256, 256>>>();

    // 4. clear scratch (acc2/slotmap/bitmap/deg2/counter)
    clear_kernel<<<(CLR_TOTAL + 255) / 256, 256>>>();

    // 5. GEMM2: gl = h1@W2l ; gr = h1@W2r + b2
    mma_gemm2<<<391, 256, 83968>>>(p_B2h, p_B2l, b2, p_gl, p_gr, NNODES);

    // 6. slot assignment + bitmap
    slot_kernel<<<(BGRAPH * (AREG + 1) + 255) / 256, 256>>>(targets, regions);

    // 7. conv2 scatter with smem bitmap filter
    {
        dim3 grid(125, BGRAPH);
        scatter2_kernel<<<grid, 320>>>(ne);
    }

    // 8. u_b = Wo @ t_b, c_b
    u_kernel<<<(BGRAPH * HDIM + 255) / 256, 256>>>(targets, Wo, bo);

    // 9. h2r materialization
    h2r_kernel<<<(NREG / 2 * 32 + 255) / 256, 256>>>(regions);

    // 10. readout GEMM
    final_mma<<<NREG / 128, 256, 92736>>>(bm, q);
}

// round 15
// speedup vs baseline: 1.4145x; 1.0047x over previous
#include <cuda_runtime.h>
#include <cuda_bf16.h>

#define NNODES 50000
#define FIN    128
#define DDIM   64
#define HDIM   128
#define BGRAPH 16
#define E1N    800000
#define E2N    200000
#define AREG   2000
#define NREG   (BGRAPH * AREG)   // 32000
#define SLOTS  2048
#define BMWORDS 1568
#define DEGCAP 96

typedef unsigned long long ull;
typedef unsigned int u32;

// ---------------- helpers -------------------------------------------------------
__device__ __forceinline__ u32 bf2_hi(float a, float b) {
    __nv_bfloat162 h = __floats2bfloat162_rn(a, b);
    return *reinterpret_cast<u32*>(&h);
}
__device__ __forceinline__ u32 bf2_lo(float a, float b) {
    float ra = a - __bfloat162float(__float2bfloat16(a));
    float rb = b - __bfloat162float(__float2bfloat16(b));
    __nv_bfloat162 l = __floats2bfloat162_rn(ra, rb);
    return *reinterpret_cast<u32*>(&l);
}
__device__ __forceinline__ void mma16816(float* c, u32 a0, u32 a1, u32 a2, u32 a3,
                                         u32 b0, u32 b1) {
    asm("mma.sync.aligned.m16n8k16.row.col.f32.bf16.bf16.f32 "
        "{%0,%1,%2,%3}, {%4,%5,%6,%7}, {%8,%9}, {%0,%1,%2,%3};"
        : "+f"(c[0]), "+f"(c[1]), "+f"(c[2]), "+f"(c[3])
        : "r"(a0), "r"(a1), "r"(a2), "r"(a3), "r"(b0), "r"(b1));
}
__device__ __forceinline__ u32 smem_u32(const void* p) {
    u32 a;
    asm("{ .reg .u64 t; cvta.to.shared.u64 t, %1; cvt.u32.u64 %0, t; }"
        : "=r"(a) : "l"(p));
    return a;
}
__device__ __forceinline__ void cpa16(u32 smem_addr, const void* gptr) {
    asm volatile("cp.async.cg.shared.global [%0], [%1], 16;"
                 :: "r"(smem_addr), "l"(gptr) : "memory");
}
__device__ __forceinline__ void cpa16z(u32 smem_addr, const void* gptr, u32 sz) {
    asm volatile("cp.async.cg.shared.global [%0], [%1], 16, %2;"
                 :: "r"(smem_addr), "l"(gptr), "r"(sz) : "memory");
}
#define CP_COMMIT() asm volatile("cp.async.commit_group;" ::: "memory")
#define CP_WAIT0()  asm volatile("cp.async.wait_group 0;" ::: "memory")

__host__ __device__ __forceinline__ int pp_of(int jg) {
    return ((jg >> 2) & 1) + (jg & 3) * 2 + (jg >> 3) * 8;
}

// ---------------- scratch -------------------------------------------------------
__device__ __align__(16) float d_yl[NNODES * DDIM];
__device__ __align__(16) float d_yr[NNODES * DDIM];
__device__ __align__(16) float d_h1[NNODES * DDIM];
__device__ __align__(16) int   d_cnt[NNODES];
__device__ __align__(16) int   d_csr[NNODES * DEGCAP];
__device__ __align__(16) float d_gl[NNODES * DDIM];
__device__ __align__(16) float d_gr[NNODES * DDIM];
__device__ __align__(16) int   d_slotmap[BGRAPH * NNODES];
__device__ __align__(16) unsigned d_bitmap[BGRAPH * BMWORDS];
__device__ __align__(16) int   d_counter[BGRAPH];
__device__ __align__(16) float d_acc2[BGRAPH * SLOTS * DDIM];
__device__ __align__(16) float d_deg2[BGRAPH * SLOTS];
__device__ __align__(16) float d_u[BGRAPH * HDIM];
__device__ __align__(16) float d_c[BGRAPH];
// preconverted weights (pair-permuted bf16 split; chunk-major [c][n][24])
__device__ __align__(16) u32 d_B1h[4 * 128 * 24];
__device__ __align__(16) u32 d_B1l[4 * 128 * 24];
__device__ __align__(16) u32 d_B2h[2 * 128 * 24];
__device__ __align__(16) u32 d_B2l[2 * 128 * 24];
__device__ __align__(16) u32 d_Wmh[2 * 128 * 24];
__device__ __align__(16) u32 d_Wml[2 * 128 * 24];

// ---------------- init kernel: clears + weight preconversion --------------------
static constexpr int CLR_ACC2 = BGRAPH * SLOTS * DDIM / 4;
static constexpr int CLR_SMAP = BGRAPH * NNODES / 4;
static constexpr int CLR_BMAP = BGRAPH * BMWORDS / 4;
static constexpr int CLR_DEG2 = BGRAPH * SLOTS / 4;
static constexpr int CLR_CNT  = BGRAPH / 4;
static constexpr int CLR_CNT1 = NNODES / 4;
static constexpr int INIT_W   = 1024;
static constexpr int INIT_TOTAL = CLR_ACC2 + CLR_SMAP + CLR_BMAP + CLR_DEG2 +
                                  CLR_CNT + CLR_CNT1 + INIT_W;

__global__ void init_kernel(const float* __restrict__ W1l,
                            const float* __restrict__ W1r,
                            const float* __restrict__ W2l,
                            const float* __restrict__ W2r,
                            const float* __restrict__ Wm) {
    int i = blockIdx.x * blockDim.x + threadIdx.x;
    float4 z = make_float4(0.f, 0.f, 0.f, 0.f);
    if (i < CLR_ACC2) { ((float4*)d_acc2)[i] = z; return; }
    i -= CLR_ACC2;
    if (i < CLR_SMAP) { ((int4*)d_slotmap)[i] = make_int4(-1, -1, -1, -1); return; }
    i -= CLR_SMAP;
    if (i < CLR_BMAP) { ((uint4*)d_bitmap)[i] = make_uint4(0, 0, 0, 0); return; }
    i -= CLR_BMAP;
    if (i < CLR_DEG2) { ((float4*)d_deg2)[i] = z; return; }
    i -= CLR_DEG2;
    if (i < CLR_CNT)  { ((int4*)d_counter)[i] = make_int4(0, 0, 0, 0); return; }
    i -= CLR_CNT;
    if (i < CLR_CNT1) { ((int4*)d_cnt)[i] = make_int4(0, 0, 0, 0); return; }
    i -= CLR_CNT1;
    if (i >= INIT_W) return;
    // weight preconversion
    if (i < 512) {
        int c = i >> 7, n = i & 127;
        const float* W = (n < 64) ? W1l : W1r;
        int nc = n & 63;
        u32* oh = d_B1h + (c * 128 + n) * 24;
        u32* ol = d_B1l + (c * 128 + n) * 24;
#pragma unroll
        for (int jg = 0; jg < 16; jg++) {
            int k = c * 32 + 2 * jg;
            float wx = W[k * 64 + nc];
            float wy = W[(k + 1) * 64 + nc];
            int pp = pp_of(jg);
            oh[pp] = bf2_hi(wx, wy);
            ol[pp] = bf2_lo(wx, wy);
        }
    } else if (i < 768) {
        int id = i - 512;
        int c = id >> 7, n = id & 127;
        const float* W = (n < 64) ? W2l : W2r;
        int nc = n & 63;
        u32* oh = d_B2h + (c * 128 + n) * 24;
        u32* ol = d_B2l + (c * 128 + n) * 24;
#pragma unroll
        for (int jg = 0; jg < 16; jg++) {
            int k = c * 32 + 2 * jg;
            float wx = W[k * 64 + nc];
            float wy = W[(k + 1) * 64 + nc];
            int pp = pp_of(jg);
            oh[pp] = bf2_hi(wx, wy);
            ol[pp] = bf2_lo(wx, wy);
        }
    } else {
        int id = i - 768;
        int c = id >> 7, n = id & 127;
        u32* oh = d_Wmh + (c * 128 + n) * 24;
        u32* ol = d_Wml + (c * 128 + n) * 24;
#pragma unroll
        for (int jg = 0; jg < 16; jg++) {
            int k = c * 32 + 2 * jg;
            float wx = Wm[k * 128 + n];
            float wy = Wm[(k + 1) * 128 + n];
            int pp = pp_of(jg);
            oh[pp] = bf2_hi(wx, wy);
            ol[pp] = bf2_lo(wx, wy);
        }
    }
}

// ---------------- conv1 bucket fill ---------------------------------------------
__global__ void fill_kernel(const int* __restrict__ ei) {
    int idx = (blockIdx.x * blockDim.x + threadIdx.x) * 4;
    if (idx >= E1N) return;
    int4 s = *(const int4*)(ei + idx);
    int4 d = *(const int4*)(ei + E1N + idx);
    int o0 = atomicAdd(&d_cnt[d.x], 1);
    int o1 = atomicAdd(&d_cnt[d.y], 1);
    int o2 = atomicAdd(&d_cnt[d.z], 1);
    int o3 = atomicAdd(&d_cnt[d.w], 1);
    d_csr[d.x * DEGCAP + o0] = s.x;
    d_csr[d.y * DEGCAP + o1] = s.y;
    d_csr[d.z * DEGCAP + o2] = s.z;
    d_csr[d.w * DEGCAP + o3] = s.w;
}

// ---------------- conv1 gather: index-batched -----------------------------------
__global__ void gather1_kernel() {
    int tid = blockIdx.x * blockDim.x + threadIdx.x;
    int w = tid >> 5, lane = tid & 31;
    int node = 2 * w + (lane >> 4);
    int j = lane & 15;
    int deg = d_cnt[node];
    const int4* csr4 = (const int4*)(d_csr + node * DEGCAP);
    float4 acc = make_float4(0.f, 0.f, 0.f, 0.f);
    for (int i0 = 0; i0 < deg; i0 += 16) {
        int q = i0 >> 2;
        int4 a = csr4[q], b = csr4[q + 1], c = csr4[q + 2], d4 = csr4[q + 3];
        int idx[16] = {a.x, a.y, a.z, a.w, b.x, b.y, b.z, b.w,
                       c.x, c.y, c.z, c.w, d4.x, d4.y, d4.z, d4.w};
#pragma unroll
        for (int u = 0; u < 16; u++) {
            if (i0 + u < deg) {
                float4 v = ((const float4*)(d_yl + idx[u] * 64))[j];
                acc.x += v.x; acc.y += v.y; acc.z += v.z; acc.w += v.w;
            }
        }
    }
    float inv = 1.f / fmaxf((float)deg, 1.f);
    float4 y = ((const float4*)(d_yr + node * 64))[j];
    float4 h;
    h.x = fmaxf(acc.x * inv + y.x, 0.f);
    h.y = fmaxf(acc.y * inv + y.y, 0.f);
    h.z = fmaxf(acc.z * inv + y.z, 0.f);
    h.w = fmaxf(acc.w * inv + y.w, 0.f);
    ((float4*)(d_h1 + node * 64))[j] = h;
}

// ================= GEMM1: D[128,128] = x @ [W1l|W1r], cp.async 2-buffer =========
__global__ __launch_bounds__(256) void mma_gemm1(const float* __restrict__ X,
                                                 const u32* __restrict__ Bgh,
                                                 const u32* __restrict__ Bgl,
                                                 const float* __restrict__ bias,
                                                 float* __restrict__ C1,
                                                 float* __restrict__ C2,
                                                 int nrows) {
    extern __shared__ u32 sm[];
    const int t = threadIdx.x;
    const int w = t >> 5, lane = t & 31;
    const int g = lane >> 2, tg = lane & 3;
    const int row0 = blockIdx.x * 128;

    float acc[16][4];
#pragma unroll
    for (int nt = 0; nt < 16; nt++)
#pragma unroll
        for (int i = 0; i < 4; i++) acc[nt][i] = 0.f;

    auto copy_chunk = [&](int c, int buf) {
        u32 sbase = smem_u32(sm + buf * 10752);
#pragma unroll
        for (int i = 0; i < 4; i++) {
            int idx = t + i * 256;
            int row = idx >> 3, gc = idx & 7;
            int grow = row0 + row;
            u32 sz = (grow < nrows) ? 16u : 0u;
            const float* src = X + (long)min(grow, nrows - 1) * 128 + c * 32 + gc * 4;
            cpa16z(sbase + (row * 36 + gc * 4) * 4, src, sz);
        }
#pragma unroll
        for (int i = 0; i < 3; i++) {
            int idx = t + i * 256;
            cpa16(sbase + 4608 * 4 + idx * 16, Bgh + c * 3072 + idx * 4);
            cpa16(sbase + 7680 * 4 + idx * 16, Bgl + c * 3072 + idx * 4);
        }
        CP_COMMIT();
    };

    copy_chunk(0, 0);

#pragma unroll
    for (int c = 0; c < 4; c++) {
        CP_WAIT0();
        __syncthreads();
        if (c + 1 < 4) copy_chunk(c + 1, (c + 1) & 1);

        const float* sAf = (const float*)(sm + (c & 1) * 10752);
        const __nv_bfloat16* sBh = (const __nv_bfloat16*)(sm + (c & 1) * 10752 + 4608);
        const __nv_bfloat16* sBl = (const __nv_bfloat16*)(sm + (c & 1) * 10752 + 7680);

#pragma unroll
        for (int ks = 0; ks < 2; ks++) {
            const float* Ar0 = sAf + (w * 16 + g) * 36 + ks * 16 + 2 * tg;
            const float* Ar1 = Ar0 + 8 * 36;
            float2 p00 = *(const float2*)Ar0;
            float2 p02 = *(const float2*)(Ar0 + 8);
            float2 p10 = *(const float2*)Ar1;
            float2 p12 = *(const float2*)(Ar1 + 8);
            u32 h0 = bf2_hi(p00.x, p00.y), h2 = bf2_hi(p02.x, p02.y);
            u32 h1 = bf2_hi(p10.x, p10.y), h3 = bf2_hi(p12.x, p12.y);
            u32 l0 = bf2_lo(p00.x, p00.y), l2 = bf2_lo(p02.x, p02.y);
            u32 l1 = bf2_lo(p10.x, p10.y), l3 = bf2_lo(p12.x, p12.y);
#pragma unroll
            for (int nt = 0; nt < 16; nt++) {
                ull bh = *(const ull*)(sBh + (nt * 8 + g) * 48 + ks * 16 + tg * 4);
                u32 bh0 = (u32)bh, bh1 = (u32)(bh >> 32);
                mma16816(acc[nt], h0, h1, h2, h3, bh0, bh1);
                mma16816(acc[nt], l0, l1, l2, l3, bh0, bh1);
                ull bl = *(const ull*)(sBl + (nt * 8 + g) * 48 + ks * 16 + tg * 4);
                mma16816(acc[nt], h0, h1, h2, h3, (u32)bl, (u32)(bl >> 32));
            }
        }
        __syncthreads();
    }

    int r0 = row0 + w * 16 + g;
#pragma unroll
    for (int nt = 0; nt < 16; nt++) {
        int col = nt * 8 + tg * 2;
        if (col < 64) {
            if (r0 < nrows)
                *(float2*)(C1 + (long)r0 * 64 + col) = make_float2(acc[nt][0], acc[nt][1]);
            if (r0 + 8 < nrows)
                *(float2*)(C1 + (long)(r0 + 8) * 64 + col) = make_float2(acc[nt][2], acc[nt][3]);
        } else {
            int c2 = col - 64;
            float2 bb = *(const float2*)(bias + c2);
            if (r0 < nrows)
                *(float2*)(C2 + (long)r0 * 64 + c2) =
                    make_float2(acc[nt][0] + bb.x, acc[nt][1] + bb.y);
            if (r0 + 8 < nrows)
                *(float2*)(C2 + (long)(r0 + 8) * 64 + c2) =
                    make_float2(acc[nt][2] + bb.x, acc[nt][3] + bb.y);
        }
    }
}

// ================= GEMM2: D = h1 @ [W2l|W2r], single upfront load ===============
__global__ __launch_bounds__(256) void mma_gemm2(const u32* __restrict__ Bgh,
                                                 const u32* __restrict__ Bgl,
                                                 const float* __restrict__ bias,
                                                 float* __restrict__ C1,
                                                 float* __restrict__ C2,
                                                 int nrows) {
    extern __shared__ u32 sm[];
    const int t = threadIdx.x;
    const int w = t >> 5, lane = t & 31;
    const int g = lane >> 2, tg = lane & 3;
    const int row0 = blockIdx.x * 128;

    {
        u32 sh = smem_u32(sm);
#pragma unroll
        for (int i = 0; i < 8; i++) {
            int idx = t + i * 256;
            int row = idx >> 4, gc = idx & 15;
            int grow = row0 + row;
            u32 sz = (grow < nrows) ? 16u : 0u;
            cpa16z(sh + (row * 68 + gc * 4) * 4,
                   d_h1 + (long)min(grow, nrows - 1) * 64 + gc * 4, sz);
        }
        u32 sb = smem_u32(sm + 8704);
#pragma unroll
        for (int i = 0; i < 6; i++) {
            int idx = t + i * 256;
            cpa16(sb + idx * 16, Bgh + idx * 4);
            cpa16(sb + 6144 * 4 + idx * 16, Bgl + idx * 4);
        }
        CP_COMMIT();
        CP_WAIT0();
        __syncthreads();
    }

    float acc[16][4];
#pragma unroll
    for (int nt = 0; nt < 16; nt++)
#pragma unroll
        for (int i = 0; i < 4; i++) acc[nt][i] = 0.f;

    const float* sH = (const float*)sm;

#pragma unroll
    for (int c = 0; c < 2; c++) {
        const __nv_bfloat16* sBh = (const __nv_bfloat16*)(sm + 8704 + c * 3072);
        const __nv_bfloat16* sBl = (const __nv_bfloat16*)(sm + 14848 + c * 3072);
#pragma unroll
        for (int ks = 0; ks < 2; ks++) {
            const float* Ar0 = sH + (w * 16 + g) * 68 + c * 32 + ks * 16 + 2 * tg;
            const float* Ar1 = Ar0 + 8 * 68;
            float2 p00 = *(const float2*)Ar0;
            float2 p02 = *(const float2*)(Ar0 + 8);
            float2 p10 = *(const float2*)Ar1;
            float2 p12 = *(const float2*)(Ar1 + 8);
            u32 h0 = bf2_hi(p00.x, p00.y), h2 = bf2_hi(p02.x, p02.y);
            u32 h1 = bf2_hi(p10.x, p10.y), h3 = bf2_hi(p12.x, p12.y);
            u32 l0 = bf2_lo(p00.x, p00.y), l2 = bf2_lo(p02.x, p02.y);
            u32 l1 = bf2_lo(p10.x, p10.y), l3 = bf2_lo(p12.x, p12.y);
#pragma unroll
            for (int nt = 0; nt < 16; nt++) {
                ull bh = *(const ull*)(sBh + (nt * 8 + g) * 48 + ks * 16 + tg * 4);
                u32 bh0 = (u32)bh, bh1 = (u32)(bh >> 32);
                mma16816(acc[nt], h0, h1, h2, h3, bh0, bh1);
                mma16816(acc[nt], l0, l1, l2, l3, bh0, bh1);
                ull bl = *(const ull*)(sBl + (nt * 8 + g) * 48 + ks * 16 + tg * 4);
                mma16816(acc[nt], h0, h1, h2, h3, (u32)bl, (u32)(bl >> 32));
            }
        }
    }

    int r0 = row0 + w * 16 + g;
#pragma unroll
    for (int nt = 0; nt < 16; nt++) {
        int col = nt * 8 + tg * 2;
        if (col < 64) {
            if (r0 < nrows)
                *(float2*)(C1 + (long)r0 * 64 + col) = make_float2(acc[nt][0], acc[nt][1]);
            if (r0 + 8 < nrows)
                *(float2*)(C1 + (long)(r0 + 8) * 64 + col) = make_float2(acc[nt][2], acc[nt][3]);
        } else {
            int c2 = col - 64;
            float2 bb = *(const float2*)(bias + c2);
            if (r0 < nrows)
                *(float2*)(C2 + (long)r0 * 64 + c2) =
                    make_float2(acc[nt][0] + bb.x, acc[nt][1] + bb.y);
            if (r0 + 8 < nrows)
                *(float2*)(C2 + (long)(r0 + 8) * 64 + c2) =
                    make_float2(acc[nt][2] + bb.x, acc[nt][3] + bb.y);
        }
    }
}

// ---------------- slot assignment + bitmap --------------------------------------
__global__ void slot_kernel(const int* __restrict__ targets,
                            const int* __restrict__ regions) {
    int idx = blockIdx.x * blockDim.x + threadIdx.x;
    if (idx >= BGRAPH * (AREG + 1)) return;
    int b = idx / (AREG + 1);
    int j = idx % (AREG + 1);
    int node = (j == AREG) ? targets[b] : regions[b * AREG + j];
    atomicOr(&d_bitmap[b * BMWORDS + (node >> 5)], 1u << (node & 31));
    int* p = &d_slotmap[b * NNODES + node];
    if (atomicCAS(p, -1, -2) == -1) {
        int s = atomicAdd(&d_counter[b], 1);
        atomicExch(p, s);
    }
}

// ---------------- conv2 scatter with smem bitmap filter -------------------------
__global__ void scatter2_kernel(const int* __restrict__ ne) {
    __shared__ unsigned sbm[BMWORDS];
    const int b = blockIdx.y;
    for (int i = threadIdx.x; i < BMWORDS; i += 320)
        sbm[i] = d_bitmap[b * BMWORDS + i];
    __syncthreads();

    const int lane = threadIdx.x & 31;
    const long base = (long)b * 2 * E2N;
    int e0 = blockIdx.x * 1600 + threadIdx.x;
#pragma unroll
    for (int it = 0; it < 5; it++) {
        int e = e0 + it * 320;
        int dst = ne[base + E2N + e];
        bool hit = (sbm[dst >> 5] >> (dst & 31)) & 1u;
        int slot = -1, src = 0;
        if (hit) {
            slot = d_slotmap[b * NNODES + dst];
            src = ne[base + e];
        }
        unsigned mask = __ballot_sync(0xffffffffu, hit);
        while (mask) {
            int bit = __ffs(mask) - 1;
            mask &= mask - 1;
            int es = __shfl_sync(0xffffffffu, src, bit);
            int sl = __shfl_sync(0xffffffffu, slot, bit);
            float2 v = ((const float2*)(d_gl + es * 64))[lane];
            float* p = d_acc2 + (b * SLOTS + sl) * 64 + 2 * lane;
            asm volatile("red.global.add.v2.f32 [%0], {%1,%2};"
                         :: "l"(p), "f"(v.x), "f"(v.y) : "memory");
            if (lane == 0) atomicAdd(&d_deg2[b * SLOTS + sl], 1.0f);
        }
    }
}

// ---------------- u_b = Wo @ t_b , c_b = bo . t_b -------------------------------
__global__ void u_kernel(const int* __restrict__ targets,
                         const float* __restrict__ Wo,
                         const float* __restrict__ bo) {
    int idx = blockIdx.x * blockDim.x + threadIdx.x;
    if (idx >= BGRAPH * HDIM) return;
    int b = idx >> 7;
    int h = idx & 127;
    int node = targets[b];
    int s = d_slotmap[b * NNODES + node];
    int base = (b * SLOTS + s) * 64;
    float inv = 1.f / fmaxf(d_deg2[b * SLOTS + s], 1.f);
    float acc = 0.f, c = 0.f;
#pragma unroll
    for (int d = 0; d < 64; d++) {
        float td = fmaxf(d_acc2[base + d] * inv + d_gr[node * 64 + d], 0.f);
        acc += Wo[h * 64 + d] * td;
        c += bo[d] * td;
    }
    d_u[idx] = acc;
    if (h == 0) d_c[b] = c;
}

// ================= final readout as HMMA GEMM (h2 computed in loader) ===========
// Per CTA: rows = 128 region positions, E = relu(h2 @ Wm + bm) [128, 128],
// q[p] = E[p,:] . u[b(p),:] + c[b(p)].
// smem (u32): sH 8704 | sBh 6144 | sBl 6144 | su 2048 | sbm 128 | sc 16 = 23184
__global__ __launch_bounds__(256) void final_mma(const int* __restrict__ regions,
                                                 const float* __restrict__ bm,
                                                 float* __restrict__ q) {
    extern __shared__ u32 sm[];
    const int t = threadIdx.x;
    const int w = t >> 5, lane = t & 31;
    const int g = lane >> 2, tg = lane & 3;
    const int row0 = blockIdx.x * 128;

    // async stage: Wm slabs, u, bm, c
    {
        u32 sb = smem_u32(sm + 8704);
#pragma unroll
        for (int i = 0; i < 6; i++) {
            int idx = t + i * 256;
            cpa16(sb + idx * 16, d_Wmh + idx * 4);
            cpa16(sb + 6144 * 4 + idx * 16, d_Wml + idx * 4);
        }
        u32 su = smem_u32(sm + 20992);
#pragma unroll
        for (int i = 0; i < 2; i++) {
            int idx = t + i * 256;
            cpa16(su + idx * 16, d_u + idx * 4);
        }
        if (t < 32) cpa16(smem_u32(sm + 23040) + t * 16, bm + t * 4);
        if (t < 4)  cpa16(smem_u32(sm + 23168) + t * 16, d_c + t * 4);
        CP_COMMIT();
    }

    // compute h2 rows directly into smem (overlaps the cp.asyncs)
    {
        int row = t >> 1, half = t & 1;        // 128 rows x 2 halves
        int p = row0 + row;
        int b = p / AREG;
        int node = regions[p];
        int s = d_slotmap[b * NNODES + node];
        int base = (b * SLOTS + s) * 64 + half * 32;
        float inv = 1.f / fmaxf(d_deg2[b * SLOTS + s], 1.f);
        const float4* ap = (const float4*)(d_acc2 + base);
        const float4* gp = (const float4*)(d_gr + node * 64 + half * 32);
        float4* dst = (float4*)((float*)sm + row * 68 + half * 32);
#pragma unroll
        for (int i = 0; i < 8; i++) {
            float4 a = ap[i];
            float4 g4 = gp[i];
            float4 h;
            h.x = fmaxf(a.x * inv + g4.x, 0.f);
            h.y = fmaxf(a.y * inv + g4.y, 0.f);
            h.z = fmaxf(a.z * inv + g4.z, 0.f);
            h.w = fmaxf(a.w * inv + g4.w, 0.f);
            dst[i] = h;
        }
    }
    CP_WAIT0();
    __syncthreads();

    float acc[16][4];
#pragma unroll
    for (int nt = 0; nt < 16; nt++)
#pragma unroll
        for (int i = 0; i < 4; i++) acc[nt][i] = 0.f;

    const float* sH = (const float*)sm;

#pragma unroll
    for (int c = 0; c < 2; c++) {
        const __nv_bfloat16* sBh = (const __nv_bfloat16*)(sm + 8704 + c * 3072);
        const __nv_bfloat16* sBl = (const __nv_bfloat16*)(sm + 14848 + c * 3072);
#pragma unroll
        for (int ks = 0; ks < 2; ks++) {
            const float* Ar0 = sH + (w * 16 + g) * 68 + c * 32 + ks * 16 + 2 * tg;
            const float* Ar1 = Ar0 + 8 * 68;
            float2 p00 = *(const float2*)Ar0;
            float2 p02 = *(const float2*)(Ar0 + 8);
            float2 p10 = *(const float2*)Ar1;
            float2 p12 = *(const float2*)(Ar1 + 8);
            u32 h0 = bf2_hi(p00.x, p00.y), h2 = bf2_hi(p02.x, p02.y);
            u32 h1 = bf2_hi(p10.x, p10.y), h3 = bf2_hi(p12.x, p12.y);
            u32 l0 = bf2_lo(p00.x, p00.y), l2 = bf2_lo(p02.x, p02.y);
            u32 l1 = bf2_lo(p10.x, p10.y), l3 = bf2_lo(p12.x, p12.y);
#pragma unroll
            for (int nt = 0; nt < 16; nt++) {
                ull bh = *(const ull*)(sBh + (nt * 8 + g) * 48 + ks * 16 + tg * 4);
                u32 bh0 = (u32)bh, bh1 = (u32)(bh >> 32);
                mma16816(acc[nt], h0, h1, h2, h3, bh0, bh1);
                mma16816(acc[nt], l0, l1, l2, l3, bh0, bh1);
                ull bl = *(const ull*)(sBl + (nt * 8 + g) * 48 + ks * 16 + tg * 4);
                mma16816(acc[nt], h0, h1, h2, h3, (u32)bl, (u32)(bl >> 32));
            }
        }
    }

    // ---- epilogue: relu(+bm) . u[b], quad reduce, + c[b] ----
    const float* su = (const float*)(sm + 20992);
    const float* sbm = (const float*)(sm + 23040);
    const float* sc = (const float*)(sm + 23168);
    int p0 = row0 + w * 16 + g;
    int p1 = p0 + 8;
    int b0 = p0 / AREG, b1 = p1 / AREG;
    const float* u0 = su + b0 * 128;
    const float* u1 = su + b1 * 128;
    float s0 = 0.f, s1 = 0.f;
#pragma unroll
    for (int nt = 0; nt < 16; nt++) {
        int col = nt * 8 + tg * 2;
        float bx = sbm[col], by = sbm[col + 1];
        s0 += fmaxf(acc[nt][0] + bx, 0.f) * u0[col]
            + fmaxf(acc[nt][1] + by, 0.f) * u0[col + 1];
        s1 += fmaxf(acc[nt][2] + bx, 0.f) * u1[col]
            + fmaxf(acc[nt][3] + by, 0.f) * u1[col + 1];
    }
    s0 += __shfl_xor_sync(0xffffffffu, s0, 1);
    s0 += __shfl_xor_sync(0xffffffffu, s0, 2);
    s1 += __shfl_xor_sync(0xffffffffu, s1, 1);
    s1 += __shfl_xor_sync(0xffffffffu, s1, 2);
    if (tg == 0) {
        q[p0] = s0 + sc[b0];
        q[p1] = s1 + sc[b1];
    }
}

// ---------------- launch ---------------------------------------------------------
extern "C" void kernel_launch(void* const* d_in, const int* in_sizes, int n_in,
                              void* d_out, int out_size) {
    const float* x       = (const float*)d_in[0];
    const int*   ei      = (const int*)  d_in[1];
    const int*   ne      = (const int*)  d_in[2];
    const int*   targets = (const int*)  d_in[3];
    const int*   regions = (const int*)  d_in[4];
    const float* W1l     = (const float*)d_in[5];
    const float* W1r     = (const float*)d_in[6];
    const float* b1      = (const float*)d_in[7];
    const float* W2l     = (const float*)d_in[8];
    const float* W2r     = (const float*)d_in[9];
    const float* b2      = (const float*)d_in[10];
    const float* Wm      = (const float*)d_in[11];
    const float* bm      = (const float*)d_in[12];
    const float* Wo      = (const float*)d_in[13];
    const float* bo      = (const float*)d_in[14];
    float* q = (float*)d_out;

    float *p_yl, *p_yr, *p_gl, *p_gr;
    u32 *p_B1h, *p_B1l, *p_B2h, *p_B2l;
    cudaGetSymbolAddress((void**)&p_yl, d_yl);
    cudaGetSymbolAddress((void**)&p_yr, d_yr);
    cudaGetSymbolAddress((void**)&p_gl, d_gl);
    cudaGetSymbolAddress((void**)&p_gr, d_gr);
    cudaGetSymbolAddress((void**)&p_B1h, d_B1h);
    cudaGetSymbolAddress((void**)&p_B1l, d_B1l);
    cudaGetSymbolAddress((void**)&p_B2h, d_B2h);
    cudaGetSymbolAddress((void**)&p_B2l, d_B2l);

    cudaFuncSetAttribute(mma_gemm1, cudaFuncAttributeMaxDynamicSharedMemorySize, 86016);
    cudaFuncSetAttribute(mma_gemm2, cudaFuncAttributeMaxDynamicSharedMemorySize, 83968);
    cudaFuncSetAttribute(final_mma, cudaFuncAttributeMaxDynamicSharedMemorySize, 92736);

    // 0. init: clears + weight preconversion
    init_kernel<<<(INIT_TOTAL + 255) / 256, 256>>>(W1l, W1r, W2l, W2r, Wm);

    // 1. GEMM1: yl = x@W1l ; yr = x@W1r + b1
    mma_gemm1<<<391, 256, 86016>>>(x, p_B1h, p_B1l, b1, p_yl, p_yr, NNODES);

    // 2. conv1 bucket fill
    fill_kernel<<<(E1N / 4 + 255) / 256, 256>>>(ei);

    // 3. conv1 gather -> h1    <-- profiled slot
    gather1_kernel<<<(NNODES / 2 * 32) / 256, 256>>>();

    // 4. GEMM2: gl = h1@W2l ; gr = h1@W2r + b2
    mma_gemm2<<<391, 256, 83968>>>(p_B2h, p_B2l, b2, p_gl, p_gr, NNODES);

    // 5. slot assignment + bitmap
    slot_kernel<<<(BGRAPH * (AREG + 1) + 255) / 256, 256>>>(targets, regions);

    // 6. conv2 scatter with smem bitmap filter
    {
        dim3 grid(125, BGRAPH);
        scatter2_kernel<<<grid, 320>>>(ne);
    }

    // 7. u_b = Wo @ t_b, c_b
    u_kernel<<<(BGRAPH * HDIM + 255) / 256, 256>>>(targets, Wo, bo);

    // 8. readout GEMM (h2 computed in loader)
    final_mma<<<NREG / 128, 256, 92736>>>(regions, bm, q);
}